// round 15
// baseline (speedup 1.0000x reference)
#include <cuda_runtime.h>
#include <cuda_fp16.h>
#include <stdint.h>
#include <math.h>

#define BB     4
#define TT     4096
#define HID    2048
#define NHEADS 16
#define HDIM   128
#define INTER  8192
#define KSEL   512
#define NTOK   (BB*KSEL)
#define NTOT   (BB*TT)
#define CH     (HID/4)
#define QSTR   (3*HID)   // 6144

// B-buffer regions (halves)
#define OFF_CFC1 ((size_t)0)
#define OFF_QKV  ((size_t)CH*HID)
#define OFF_O    (OFF_QKV + (size_t)3*HID*HID)
#define OFF_GATE (OFF_O + (size_t)HID*HID)
#define OFF_UP   (OFF_GATE + (size_t)INTER*HID)
#define OFF_DOWN (OFF_UP + (size_t)INTER*HID)
#define B_TOTAL  (OFF_DOWN + (size_t)INTER*HID)

// ================= helpers =================
__device__ __forceinline__ uint32_t smem_to_u32(const void* p) {
    uint32_t a;
    asm("{ .reg .u64 t; cvta.to.shared.u64 t, %1; cvt.u32.u64 %0, t; }" : "=r"(a) : "l"(p));
    return a;
}
__device__ __forceinline__ void cp16(uint32_t s, const void* g) {
    asm volatile("cp.async.cg.shared.global [%0], [%1], 16;" :: "r"(s), "l"(g));
}
__device__ __forceinline__ void ldsm_x4(uint32_t* r, uint32_t addr) {
    asm volatile("ldmatrix.sync.aligned.m8n8.x4.shared.b16 {%0,%1,%2,%3}, [%4];"
        : "=r"(r[0]), "=r"(r[1]), "=r"(r[2]), "=r"(r[3]) : "r"(addr));
}
__device__ __forceinline__ void ldsm_x4_t(uint32_t* r, uint32_t addr) {
    asm volatile("ldmatrix.sync.aligned.m8n8.x4.trans.shared.b16 {%0,%1,%2,%3}, [%4];"
        : "=r"(r[0]), "=r"(r[1]), "=r"(r[2]), "=r"(r[3]) : "r"(addr));
}
__device__ __forceinline__ void mma16816(float* d, const uint32_t* a, const uint32_t* b) {
    asm volatile(
        "mma.sync.aligned.m16n8k16.row.col.f32.f16.f16.f32 "
        "{%0,%1,%2,%3}, {%4,%5,%6,%7}, {%8,%9}, {%0,%1,%2,%3};"
        : "+f"(d[0]), "+f"(d[1]), "+f"(d[2]), "+f"(d[3])
        : "r"(a[0]), "r"(a[1]), "r"(a[2]), "r"(a[3]), "r"(b[0]), "r"(b[1]));
}
__device__ __forceinline__ uint32_t packh2(float a, float b) {
    __half2 p = __floats2half2_rn(a, b);
    return *(uint32_t*)&p;
}

// ================= device scratch =================
__device__ float g_logits[NTOT];
__device__ float g_flags[NTOT];
__device__ int   g_idx[BB*KSEL];
__device__ float g_gate[BB*KSEL];
__device__ float g_act[NTOT*CH];
__device__ float g_x [NTOK*HID];
__device__ float g_h1[NTOK*HID];
__device__ float g_gu[(size_t)NTOK*INTER];   // gate pre-activation, fp32
__device__ float g_qkvb[QSTR];
__device__ double g_f0sum, g_selsum, g_predsum;
__device__ __half g_A [33554432];
__device__ __half g_Ap[33554432];
__device__ __half g_B [B_TOTAL];
__device__ __half g_qkvh[16777216];          // QKV, then reused as silu-out [NTOK, INTER]

// ================= small kernels =================
__global__ void k_init() {
    int i = blockIdx.x*blockDim.x + threadIdx.x;
    if (i < NTOT) g_flags[i] = 0.f;
    if (i == 0) { g_f0sum = 0.0; g_selsum = 0.0; g_predsum = 0.0; }
}

__global__ void k_router(const float* __restrict__ hs, const float* __restrict__ rw) {
    int t = blockIdx.x;
    const float* row = hs + (size_t)t*HID;
    float s = 0.f;
    for (int i = threadIdx.x; i < HID; i += 256) s += row[i]*rw[i];
    __shared__ float red[256];
    red[threadIdx.x] = s; __syncthreads();
    for (int st = 128; st; st >>= 1) {
        if (threadIdx.x < st) red[threadIdx.x] += red[threadIdx.x+st];
        __syncthreads();
    }
    if (threadIdx.x == 0) {
        float l = red[0];
        g_logits[t] = l;
        float f0 = fmaxf(l, 0.f) + log1pf(expf(-fabsf(l)));
        atomicAdd(&g_f0sum, (double)f0);
    }
}

// ---- radix-select top-KSEL (exact; ties -> lowest index; idx emitted ascending) ----
__global__ void k_topk() {
    int b = blockIdx.x, tid = threadIdx.x;
    __shared__ uint32_t su[TT];
    __shared__ float    sf[TT];
    __shared__ int      hist[256];
    __shared__ int      scan[1024];
    __shared__ uint32_t s_prefix;
    __shared__ int      s_kneed;

    for (int i = tid; i < TT; i += 1024) {
        float x = g_logits[b*TT + i];
        uint32_t bits = __float_as_uint(x);
        uint32_t u = bits ^ ((bits & 0x80000000u) ? 0xFFFFFFFFu : 0x80000000u);
        su[i] = u; sf[i] = x;
    }
    __syncthreads();

    uint32_t prefix = 0; int kneed = KSEL;
    for (int pass = 0; pass < 4; ++pass) {
        int shift = 24 - pass*8;
        uint32_t pmask = (pass == 0) ? 0u : (0xFFFFFFFFu << (32 - pass*8));
        if (tid < 256) hist[tid] = 0;
        __syncthreads();
        for (int i = tid; i < TT; i += 1024) {
            uint32_t u = su[i];
            if ((u & pmask) == prefix) atomicAdd(&hist[(u >> shift) & 255], 1);
        }
        __syncthreads();
        if (tid == 0) {
            int cum = 0, bsel = 0;
            for (int bin = 255; bin >= 0; --bin) {
                int c = hist[bin];
                if (cum + c >= kneed) { bsel = bin; break; }
                cum += c;
            }
            s_prefix = prefix | ((uint32_t)bsel << shift);
            s_kneed = kneed - cum;
        }
        __syncthreads();
        prefix = s_prefix; kneed = s_kneed;
        __syncthreads();
    }
    const uint32_t uthr = prefix;

    int i0 = tid*4;
    bool gt4[4], eq4[4];
    int eqc = 0;
#pragma unroll
    for (int j = 0; j < 4; j++) {
        uint32_t u = su[i0 + j];
        gt4[j] = (u > uthr); eq4[j] = (u == uthr);
        eqc += eq4[j];
    }
    scan[tid] = eqc; __syncthreads();
    for (int off = 1; off < 1024; off <<= 1) {
        int v = scan[tid];
        int va = (tid >= off) ? scan[tid - off] : 0;
        __syncthreads();
        scan[tid] = v + va;
        __syncthreads();
    }
    int eqbase = scan[tid] - eqc;

    bool sel4[4];
    int selc = 0, myeq = 0;
#pragma unroll
    for (int j = 0; j < 4; j++) {
        bool s = gt4[j];
        if (eq4[j]) { if (eqbase + myeq < kneed) s = true; myeq++; }
        sel4[j] = s; selc += s;
    }
    __syncthreads();
    scan[tid] = selc; __syncthreads();
    for (int off = 1; off < 1024; off <<= 1) {
        int v = scan[tid];
        int va = (tid >= off) ? scan[tid - off] : 0;
        __syncthreads();
        scan[tid] = v + va;
        __syncthreads();
    }
    int pos = scan[tid] - selc;

    double lsum = 0.0;
#pragma unroll
    for (int j = 0; j < 4; j++) {
        if (sel4[j]) {
            int i = i0 + j;
            float val = sf[i];
            g_idx[b*KSEL + pos] = i;
            g_gate[b*KSEL + pos] = 1.f/(1.f + expf(-val));
            g_flags[b*TT + i] = 1.f;
            lsum += (double)val;
            pos++;
        }
    }
    if (lsum != 0.0) atomicAdd(&g_selsum, lsum);
}

__global__ void k_pred2(const float* __restrict__ w2, const float* __restrict__ b2) {
    int warp = threadIdx.x >> 5, lane = threadIdx.x & 31;
    int t = blockIdx.x*8 + warp;
    const float* a = g_act + (size_t)t*CH;
    float s = 0.f;
    for (int i = lane; i < CH; i += 32) s += a[i]*w2[i];
    for (int o = 16; o; o >>= 1) s += __shfl_xor_sync(0xffffffffu, s, o);
    __shared__ float ps[8];
    if (lane == 0) {
        float p = s + b2[0];
        float tg = g_flags[t];
        ps[warp] = fmaxf(p, 0.f) - p*tg + log1pf(expf(-fabsf(p)));
    }
    __syncthreads();
    if (threadIdx.x == 0) {
        float tot = 0.f;
        for (int i = 0; i < 8; i++) tot += ps[i];
        atomicAdd(&g_predsum, (double)tot);
    }
}

// fused gather + rmsnorm1
__global__ void k_grms(const float* __restrict__ hs, const float* __restrict__ w,
                       __half* __restrict__ ha) {
    int bj = blockIdx.x, b = bj >> 9;
    int t = g_idx[bj];
    const float* src = hs + ((size_t)b*TT + t)*HID;
    int i = threadIdx.x*8;
    float4 a = *(const float4*)(src+i), bb = *(const float4*)(src+i+4);
    *(float4*)(g_x + (size_t)bj*HID + i)   = a;
    *(float4*)(g_x + (size_t)bj*HID + i+4) = bb;
    float ss = a.x*a.x + a.y*a.y + a.z*a.z + a.w*a.w
             + bb.x*bb.x + bb.y*bb.y + bb.z*bb.z + bb.w*bb.w;
    __shared__ float red[256];
    red[threadIdx.x] = ss; __syncthreads();
    for (int st = 128; st; st >>= 1) {
        if (threadIdx.x < st) red[threadIdx.x] += red[threadIdx.x+st];
        __syncthreads();
    }
    float sc = 1.f/sqrtf(red[0]/(float)HID + 1e-6f);
    float4 w0 = *(const float4*)(w+i), w1 = *(const float4*)(w+i+4);
    float v[8] = {a.x*sc*w0.x, a.y*sc*w0.y, a.z*sc*w0.z, a.w*sc*w0.w,
                  bb.x*sc*w1.x, bb.y*sc*w1.y, bb.z*sc*w1.z, bb.w*sc*w1.w};
    unsigned short hv[8];
#pragma unroll
    for (int j = 0; j < 8; j++) {
        __half hb = __float2half_rn(v[j]);
        hv[j] = *(unsigned short*)&hb;
    }
    *(uint4*)(ha + (size_t)bj*HID + i) = *(uint4*)hv;
}

__global__ void k_rms(const float* __restrict__ in, const float* __restrict__ w,
                      __half* __restrict__ ha) {
    int row = blockIdx.x;
    const float* src = in + (size_t)row*HID;
    int i = threadIdx.x*8;
    float4 a = *(const float4*)(src+i), b = *(const float4*)(src+i+4);
    float ss = a.x*a.x + a.y*a.y + a.z*a.z + a.w*a.w
             + b.x*b.x + b.y*b.y + b.z*b.z + b.w*b.w;
    __shared__ float red[256];
    red[threadIdx.x] = ss; __syncthreads();
    for (int st = 128; st; st >>= 1) {
        if (threadIdx.x < st) red[threadIdx.x] += red[threadIdx.x+st];
        __syncthreads();
    }
    float sc = 1.f/sqrtf(red[0]/(float)HID + 1e-6f);
    float4 w0 = *(const float4*)(w+i), w1 = *(const float4*)(w+i+4);
    float v[8] = {a.x*sc*w0.x, a.y*sc*w0.y, a.z*sc*w0.z, a.w*sc*w0.w,
                  b.x*sc*w1.x, b.y*sc*w1.y, b.z*sc*w1.z, b.w*sc*w1.w};
    unsigned short hv[8];
#pragma unroll
    for (int j = 0; j < 8; j++) {
        __half hb = __float2half_rn(v[j]);
        hv[j] = *(unsigned short*)&hb;
    }
    *(uint4*)(ha + (size_t)row*HID + i) = *(uint4*)hv;
}

__global__ void k_catbias(const float* __restrict__ qb, const float* __restrict__ kb,
                          const float* __restrict__ vb) {
    int i = blockIdx.x*256 + threadIdx.x;
    float v = (i < HID) ? qb[i] : (i < 2*HID ? kb[i-HID] : vb[i-2*HID]);
    g_qkvb[i] = v;
}

__global__ void k_rope() {
    int t = blockIdx.x*256 + threadIdx.x;
    int d = t & 63;
    int bh = t >> 6;
    int bj = bh >> 4, h = bh & 15;
    int pos = g_idx[bj];
    float ang = (float)pos * expf(-(float)d * 0.14391156831212787f);
    float c = cosf(ang), s = sinf(ang);
    size_t base = (size_t)bj*QSTR + h*HDIM;
    float q1 = __half2float(g_qkvh[base+d]), q2 = __half2float(g_qkvh[base+d+64]);
    g_qkvh[base+d]    = __float2half_rn(q1*c - q2*s);
    g_qkvh[base+d+64] = __float2half_rn(q2*c + q1*s);
    size_t kb = base + HID;
    float k1 = __half2float(g_qkvh[kb+d]), k2 = __half2float(g_qkvh[kb+d+64]);
    g_qkvh[kb+d]    = __float2half_rn(k1*c - k2*s);
    g_qkvh[kb+d+64] = __float2half_rn(k2*c + k1*s);
}

// ============== tensor-core flash attention ==============
#define PADQ 136
#define ATT_TB (64*PADQ*2)
#define ATT_SMEM (3*ATT_TB)

__device__ __forceinline__ void att_load_tile(uint32_t sdst, const __half* gsrc, int tid) {
#pragma unroll
    for (int u = 0; u < 8; u++) {
        int c = tid + u*128;
        int row = c >> 4, seg = (c & 15) << 3;
        cp16(sdst + (uint32_t)(row*PADQ + seg)*2, gsrc + (size_t)row*QSTR + seg);
    }
}

__global__ void __launch_bounds__(128, 1) k_attn(__half* __restrict__ oa) {
    extern __shared__ char smem[];
    uint32_t sb = smem_to_u32(smem);
    int qt = blockIdx.x, bh = blockIdx.y;
    int b = bh >> 4, h = bh & 15;
    int tid = threadIdx.x, w = tid >> 5, lane = tid & 31;

    const __half* qbase = g_qkvh + ((size_t)(b*KSEL + qt*64))*QSTR + h*HDIM;
    att_load_tile(sb, qbase, tid);
    asm volatile("cp.async.commit_group;" ::: "memory");
    asm volatile("cp.async.wait_group 0;" ::: "memory");
    __syncthreads();

    uint32_t Aq[8][4];
    {
        int arow = w*16 + (lane & 15);
        int acol = (lane >> 4) << 3;
#pragma unroll
        for (int ks = 0; ks < 8; ks++)
            ldsm_x4(Aq[ks], sb + (uint32_t)(arow*PADQ + ks*16 + acol)*2);
    }

    float co[16][4];
#pragma unroll
    for (int nt = 0; nt < 16; nt++)
#pragma unroll
        for (int i = 0; i < 4; i++) co[nt][i] = 0.f;
    float m0 = -1e30f, m1 = -1e30f, l0 = 0.f, l1 = 0.f;

    for (int kt = 0; kt <= qt; ++kt) {
        const __half* kbp = g_qkvh + ((size_t)(b*KSEL + kt*64))*QSTR + HID + h*HDIM;
        const __half* vbp = kbp + HID;
        __syncthreads();
        att_load_tile(sb + ATT_TB,   kbp, tid);
        att_load_tile(sb + 2*ATT_TB, vbp, tid);
        asm volatile("cp.async.commit_group;" ::: "memory");
        asm volatile("cp.async.wait_group 0;" ::: "memory");
        __syncthreads();

        float s[8][4];
#pragma unroll
        for (int nt = 0; nt < 8; nt++)
#pragma unroll
            for (int i = 0; i < 4; i++) s[nt][i] = 0.f;
        {
            int krow0 = (lane & 7) + ((lane >> 4) & 1)*8;
            int kcol0 = ((lane >> 3) & 1) << 3;
#pragma unroll
            for (int ks = 0; ks < 8; ks++) {
#pragma unroll
                for (int np = 0; np < 4; np++) {
                    uint32_t Kf[4];
                    ldsm_x4(Kf, sb + ATT_TB +
                        (uint32_t)((np*16 + krow0)*PADQ + ks*16 + kcol0)*2);
                    mma16816(s[2*np],   Aq[ks], Kf);
                    mma16816(s[2*np+1], Aq[ks], Kf+2);
                }
            }
        }
        const float SC = 0.08838834764831845f;
#pragma unroll
        for (int nt = 0; nt < 8; nt++)
#pragma unroll
            for (int i = 0; i < 4; i++) s[nt][i] *= SC;
        if (kt == qt) {
            int rq = w*16 + (lane >> 2);
#pragma unroll
            for (int nt = 0; nt < 8; nt++) {
                int j0 = nt*8 + 2*(lane & 3);
                if (j0   > rq)   s[nt][0] = -1e9f;
                if (j0+1 > rq)   s[nt][1] = -1e9f;
                if (j0   > rq+8) s[nt][2] = -1e9f;
                if (j0+1 > rq+8) s[nt][3] = -1e9f;
            }
        }
        float mx0 = -1e30f, mx1 = -1e30f;
#pragma unroll
        for (int nt = 0; nt < 8; nt++) {
            mx0 = fmaxf(mx0, fmaxf(s[nt][0], s[nt][1]));
            mx1 = fmaxf(mx1, fmaxf(s[nt][2], s[nt][3]));
        }
        mx0 = fmaxf(mx0, __shfl_xor_sync(0xffffffffu, mx0, 1));
        mx0 = fmaxf(mx0, __shfl_xor_sync(0xffffffffu, mx0, 2));
        mx1 = fmaxf(mx1, __shfl_xor_sync(0xffffffffu, mx1, 1));
        mx1 = fmaxf(mx1, __shfl_xor_sync(0xffffffffu, mx1, 2));
        float mn0 = fmaxf(m0, mx0), mn1 = fmaxf(m1, mx1);
        float c0 = __expf(m0 - mn0), c1 = __expf(m1 - mn1);
        float ls0 = 0.f, ls1 = 0.f;
#pragma unroll
        for (int nt = 0; nt < 8; nt++) {
            s[nt][0] = __expf(s[nt][0] - mn0); ls0 += s[nt][0];
            s[nt][1] = __expf(s[nt][1] - mn0); ls0 += s[nt][1];
            s[nt][2] = __expf(s[nt][2] - mn1); ls1 += s[nt][2];
            s[nt][3] = __expf(s[nt][3] - mn1); ls1 += s[nt][3];
        }
        ls0 += __shfl_xor_sync(0xffffffffu, ls0, 1);
        ls0 += __shfl_xor_sync(0xffffffffu, ls0, 2);
        ls1 += __shfl_xor_sync(0xffffffffu, ls1, 1);
        ls1 += __shfl_xor_sync(0xffffffffu, ls1, 2);
        l0 = l0*c0 + ls0; m0 = mn0;
        l1 = l1*c1 + ls1; m1 = mn1;
#pragma unroll
        for (int nt = 0; nt < 16; nt++) {
            co[nt][0] *= c0; co[nt][1] *= c0;
            co[nt][2] *= c1; co[nt][3] *= c1;
        }
        uint32_t Ap[4][4];
#pragma unroll
        for (int p = 0; p < 4; p++) {
            Ap[p][0] = packh2(s[2*p][0],   s[2*p][1]);
            Ap[p][1] = packh2(s[2*p][2],   s[2*p][3]);
            Ap[p][2] = packh2(s[2*p+1][0], s[2*p+1][1]);
            Ap[p][3] = packh2(s[2*p+1][2], s[2*p+1][3]);
        }
        {
            int vrow0 = lane & 15;
            int vcol0 = (lane >> 4) << 3;
#pragma unroll
            for (int ksj = 0; ksj < 4; ksj++) {
#pragma unroll
                for (int dc = 0; dc < 8; dc++) {
                    uint32_t Vf[4];
                    ldsm_x4_t(Vf, sb + 2*ATT_TB +
                        (uint32_t)((ksj*16 + vrow0)*PADQ + dc*16 + vcol0)*2);
                    mma16816(co[2*dc],   Ap[ksj], Vf);
                    mma16816(co[2*dc+1], Ap[ksj], Vf+2);
                }
            }
        }
    }
    float i0 = 1.f/l0, i1 = 1.f/l1;
    int r0 = qt*64 + w*16 + (lane >> 2);
    __half* ob = oa + ((size_t)(b*KSEL))*HID + h*HDIM;
#pragma unroll
    for (int nt = 0; nt < 16; nt++) {
        int d = nt*8 + 2*(lane & 3);
        *(uint32_t*)(ob + (size_t)r0*HID + d)     = packh2(co[nt][0]*i0, co[nt][1]*i0);
        *(uint32_t*)(ob + (size_t)(r0+8)*HID + d) = packh2(co[nt][2]*i1, co[nt][3]*i1);
    }
}

__global__ void k_copy(const float* __restrict__ src, float* __restrict__ dst) {
    size_t i = ((size_t)blockIdx.x*256 + threadIdx.x)*4;
    *(float4*)(dst+i) = *(const float4*)(src+i);
}

__global__ void k_final(float* out, long long N, long long out_size) {
    if (threadIdx.x == 0) {
        if (N   < out_size) out[N]   = (float)((g_f0sum - g_selsum)/(double)NTOT);
        if (N+1 < out_size) out[N+1] = (float)(g_predsum/(double)NTOT);
    }
}

// ======== fp32 -> fp16 cast ========
__global__ void k_convB(const float* __restrict__ src, __half* __restrict__ dst) {
    size_t base = ((size_t)blockIdx.x*256 + threadIdx.x)*8;
    const float4* s = (const float4*)(src + base);
    float4 x0 = s[0], x1 = s[1];
    float xs[8] = {x0.x, x0.y, x0.z, x0.w, x1.x, x1.y, x1.z, x1.w};
    unsigned short hv[8];
#pragma unroll
    for (int j = 0; j < 8; j++) {
        __half hb = __float2half_rn(xs[j]);
        hv[j] = *(unsigned short*)&hb;
    }
    *(uint4*)(dst + base) = *(uint4*)hv;
}

// ================= fp16 MMA GEMM =================
// epi: 0 +bias(if set); 1 gelu(acc+bias); 2 acc+add; 3 +bias write fp16;
//      5 mod-scatter: out[b,idx[m]] = x + gate*((acc+add) - x);
//      6 silu(add)*acc -> fp16 (fused up-proj epilogue)
#define PADK 40
#define A_BYTES   (128*PADK*2)
#define B_BYTES   (256*PADK*2)
#define STAGE_BYTES (A_BYTES + B_BYTES)
#define GEMM_SMEM (3*STAGE_BYTES)

__device__ __forceinline__ void load_stage(uint32_t sb, int stage,
    const __half* A, const __half* B, int K, int kt, int tid)
{
    uint32_t s0 = sb + stage*STAGE_BYTES;
#pragma unroll
    for (int u = 0; u < 2; u++) {
        int c = tid + u*256;
        int row = c >> 2, seg = (c & 3) << 3;
        cp16(s0 + (row*PADK + seg)*2, A + (size_t)row*K + (size_t)kt*32 + seg);
    }
#pragma unroll
    for (int u = 0; u < 4; u++) {
        int c = tid + u*256;
        int row = c >> 2, seg = (c & 3) << 3;
        cp16(s0 + A_BYTES + (row*PADK + seg)*2, B + (size_t)row*K + (size_t)kt*32 + seg);
    }
    asm volatile("cp.async.commit_group;" ::: "memory");
}

__global__ void __launch_bounds__(256, 1) tc_gemm(
    const __half* __restrict__ Ag, const __half* __restrict__ Bg,
    const float* __restrict__ bias, const float* __restrict__ add,
    float* __restrict__ C, int M, int N, int K, int epi)
{
    extern __shared__ __align__(16) char smem[];
    uint32_t sb = smem_to_u32(smem);
    const int tid = threadIdx.x, wid = tid >> 5, lane = tid & 31;
    const int wm = wid & 1, wn = wid >> 1;
    const long bm = (long)blockIdx.y << 7, bn = (long)blockIdx.x << 8;

    const __half* pA = Ag + (size_t)bm*K;
    const __half* pB = Bg + (size_t)bn*K;

    float acc[4][8][4];
#pragma unroll
    for (int mt = 0; mt < 4; mt++)
#pragma unroll
        for (int nt = 0; nt < 8; nt++)
#pragma unroll
            for (int i = 0; i < 4; i++) acc[mt][nt][i] = 0.f;

    const int NK = K >> 5;
    load_stage(sb, 0, pA, pB, K, 0, tid);
    load_stage(sb, 1, pA, pB, K, 1, tid);

    for (int kt = 0; kt < NK; ++kt) {
        if (kt + 2 < NK) {
            load_stage(sb, (kt+2)%3, pA, pB, K, kt+2, tid);
            asm volatile("cp.async.wait_group 2;" ::: "memory");
        } else {
            asm volatile("cp.async.wait_group 0;" ::: "memory");
        }
        __syncthreads();

        uint32_t s0 = sb + (kt%3)*STAGE_BYTES;
#pragma unroll
        for (int kk = 0; kk < 32; kk += 16) {
            uint32_t Af[4][4];
            const int arow = wm*64 + (lane & 15);
            const int acol = kk + ((lane >> 4) << 3);
#pragma unroll
            for (int mt = 0; mt < 4; mt++)
                ldsm_x4(Af[mt], s0 + (uint32_t)((arow + mt*16)*PADK + acol)*2);
            const int brow = wn*64 + (lane & 7) + (((lane >> 4) & 1) << 3);
            const int bcol = kk + (((lane >> 3) & 1) << 3);
#pragma unroll
            for (int np = 0; np < 4; np++) {
                uint32_t Bf[4];
                ldsm_x4(Bf, s0 + A_BYTES + (uint32_t)((brow + np*16)*PADK + bcol)*2);
#pragma unroll
                for (int mt = 0; mt < 4; mt++) {
                    mma16816(acc[mt][np*2],   Af[mt], Bf);
                    mma16816(acc[mt][np*2+1], Af[mt], Bf+2);
                }
            }
        }
        __syncthreads();
    }

#pragma unroll
    for (int mt = 0; mt < 4; mt++) {
#pragma unroll
        for (int nt = 0; nt < 8; nt++) {
            long m = bm + wm*64 + mt*16 + (lane >> 2);
            long n = bn + wn*64 + nt*8 + ((lane & 3) << 1);
            float* a = acc[mt][nt];
            float b0 = bias ? bias[n] : 0.f;
            float b1 = bias ? bias[n+1] : 0.f;
            float v0 = a[0] + b0, v1 = a[1] + b1, v2 = a[2] + b0, v3 = a[3] + b1;
            if (epi == 1) {
                v0 = 0.5f*v0*(1.f + erff(v0*0.70710678118654752f));
                v1 = 0.5f*v1*(1.f + erff(v1*0.70710678118654752f));
                v2 = 0.5f*v2*(1.f + erff(v2*0.70710678118654752f));
                v3 = 0.5f*v3*(1.f + erff(v3*0.70710678118654752f));
            }
            if (epi == 2) {
                v0 += add[m*N + n];     v1 += add[m*N + n + 1];
                v2 += add[(m+8)*N + n]; v3 += add[(m+8)*N + n + 1];
            }
            if (epi == 3) {
                __half* Ch = (__half*)C;
                *(uint32_t*)(Ch + m*(size_t)N + n)     = packh2(v0, v1);
                *(uint32_t*)(Ch + (m+8)*(size_t)N + n) = packh2(v2, v3);
            } else if (epi == 5) {
                long m2 = m + 8;
                float h0 = add[m*N + n],  h1v = add[m*N + n + 1];
                float h2 = add[m2*N + n], h3v = add[m2*N + n + 1];
                float x0v = g_x[m*N + n],  x1v = g_x[m*N + n + 1];
                float x2v = g_x[m2*N + n], x3v = g_x[m2*N + n + 1];
                float gt0 = g_gate[m], gt1 = g_gate[m2];
                long b0i = m >> 9,  t0 = g_idx[m];
                long b1i = m2 >> 9, t1 = g_idx[m2];
                float o0 = x0v + gt0*((v0 + h0)  - x0v);
                float o1 = x1v + gt0*((v1 + h1v) - x1v);
                float o2 = x2v + gt1*((v2 + h2)  - x2v);
                float o3 = x3v + gt1*((v3 + h3v) - x3v);
                *(float2*)(C + (b0i*TT + t0)*(long)HID + n) = make_float2(o0, o1);
                *(float2*)(C + (b1i*TT + t1)*(long)HID + n) = make_float2(o2, o3);
            } else if (epi == 6) {
                // silu(gate_preact) * acc -> fp16
                long m2 = m + 8;
                float gg0 = add[m*N + n],  gg1 = add[m*N + n + 1];
                float gg2 = add[m2*N + n], gg3 = add[m2*N + n + 1];
                float o0 = gg0/(1.f + __expf(-gg0))*v0;
                float o1 = gg1/(1.f + __expf(-gg1))*v1;
                float o2 = gg2/(1.f + __expf(-gg2))*v2;
                float o3 = gg3/(1.f + __expf(-gg3))*v3;
                __half* Ch = (__half*)C;
                *(uint32_t*)(Ch + m*(size_t)N + n)  = packh2(o0, o1);
                *(uint32_t*)(Ch + m2*(size_t)N + n) = packh2(o2, o3);
            } else {
                *(float2*)(C + m*N + n)     = make_float2(v0, v1);
                *(float2*)(C + (m+8)*N + n) = make_float2(v2, v3);
            }
        }
    }
}

// ================= launch =================
extern "C" void kernel_launch(void* const* d_in, const int* in_sizes, int n_in,
                              void* d_out, int out_size) {
    const float* hs     = (const float*)d_in[0];
    const float* rw     = (const float*)d_in[1];
    const float* cfc1_w = (const float*)d_in[2];
    const float* cfc1_b = (const float*)d_in[3];
    const float* cfc2_w = (const float*)d_in[4];
    const float* cfc2_b = (const float*)d_in[5];
    const float* ln1    = (const float*)d_in[6];
    const float* ln2    = (const float*)d_in[7];
    const float* q_w    = (const float*)d_in[8];
    const float* q_b    = (const float*)d_in[9];
    const float* k_w    = (const float*)d_in[10];
    const float* k_b    = (const float*)d_in[11];
    const float* v_w    = (const float*)d_in[12];
    const float* v_b    = (const float*)d_in[13];
    const float* o_w    = (const float*)d_in[14];
    const float* gate_w = (const float*)d_in[15];
    const float* up_w   = (const float*)d_in[16];
    const float* down_w = (const float*)d_in[17];
    float* out = (float*)d_out;

    float *px, *ph1, *pgu, *pact, *pqkvb;
    cudaGetSymbolAddress((void**)&px,  g_x);
    cudaGetSymbolAddress((void**)&ph1, g_h1);
    cudaGetSymbolAddress((void**)&pgu, g_gu);
    cudaGetSymbolAddress((void**)&pact, g_act);
    cudaGetSymbolAddress((void**)&pqkvb, g_qkvb);
    __half *pA, *pAp, *pB, *pqkvh;
    cudaGetSymbolAddress((void**)&pA,  g_A);
    cudaGetSymbolAddress((void**)&pAp, g_Ap);
    cudaGetSymbolAddress((void**)&pB,  g_B);
    cudaGetSymbolAddress((void**)&pqkvh, g_qkvh);

    cudaFuncSetAttribute(tc_gemm, cudaFuncAttributeMaxDynamicSharedMemorySize, GEMM_SMEM);
    cudaFuncSetAttribute(k_attn, cudaFuncAttributeMaxDynamicSharedMemorySize, ATT_SMEM);

    static bool s_init = false;
    static cudaStream_t s1, s2, s3;
    static cudaEvent_t e0, eTopk, eCfc1, eQkv, eO, eGate, eUp, eDown, eCopy, ePred;
    if (!s_init) {
        cudaStreamCreate(&s1); cudaStreamCreate(&s2); cudaStreamCreate(&s3);
        cudaEventCreateWithFlags(&e0,    cudaEventDisableTiming);
        cudaEventCreateWithFlags(&eTopk, cudaEventDisableTiming);
        cudaEventCreateWithFlags(&eCfc1, cudaEventDisableTiming);
        cudaEventCreateWithFlags(&eQkv,  cudaEventDisableTiming);
        cudaEventCreateWithFlags(&eO,    cudaEventDisableTiming);
        cudaEventCreateWithFlags(&eGate, cudaEventDisableTiming);
        cudaEventCreateWithFlags(&eUp,   cudaEventDisableTiming);
        cudaEventCreateWithFlags(&eDown, cudaEventDisableTiming);
        cudaEventCreateWithFlags(&eCopy, cudaEventDisableTiming);
        cudaEventCreateWithFlags(&ePred, cudaEventDisableTiming);
        s_init = true;
    }

#define CONVB_S(st, src, dst, R, K) k_convB<<<((size_t)(R)*(K)/8)/256, 256, 0, st>>>(src, dst)
#define GEMM_S(st, Ap_, Bp_, M, N, K, bias, add, Cp, epi) \
    tc_gemm<<<dim3((N)/256, (M)/128), 256, GEMM_SMEM, st>>>(Ap_, Bp_, bias, add, Cp, M, N, K, epi)

    // ---- fork ----
    k_init<<<64, 256>>>();
    cudaEventRecord(e0, 0);
    cudaStreamWaitEvent(s1, e0, 0);
    cudaStreamWaitEvent(s2, e0, 0);
    cudaStreamWaitEvent(s3, e0, 0);

    // s1: weight conversions
    CONVB_S(s1, cfc1_w, pB + OFF_CFC1, CH, HID);
    cudaEventRecord(eCfc1, s1);
    CONVB_S(s1, q_w, pB + OFF_QKV,                     HID, HID);
    CONVB_S(s1, k_w, pB + OFF_QKV + (size_t)HID*HID,   HID, HID);
    CONVB_S(s1, v_w, pB + OFF_QKV + (size_t)2*HID*HID, HID, HID);
    k_catbias<<<QSTR/256, 256, 0, s1>>>(q_b, k_b, v_b);
    cudaEventRecord(eQkv, s1);
    CONVB_S(s1, o_w, pB + OFF_O, HID, HID);
    cudaEventRecord(eO, s1);
    CONVB_S(s1, gate_w, pB + OFF_GATE, INTER, HID);
    cudaEventRecord(eGate, s1);
    CONVB_S(s1, up_w,   pB + OFF_UP,   INTER, HID);
    cudaEventRecord(eUp, s1);
    CONVB_S(s1, down_w, pB + OFF_DOWN, HID, INTER);
    cudaEventRecord(eDown, s1);

    // s2: predictor chain
    CONVB_S(s2, hs, pAp, NTOT, HID);
    cudaStreamWaitEvent(s2, eCfc1, 0);
    GEMM_S(s2, pAp, pB + OFF_CFC1, NTOT, CH, HID, cfc1_b, nullptr, pact, 1);

    // s3: bulk output copy
    k_copy<<<((size_t)NTOT*HID/4)/256, 256, 0, s3>>>(hs, out);
    cudaEventRecord(eCopy, s3);

    // main: router -> radix topk -> attention block -> MLP
    k_router<<<NTOT, 256>>>(hs, rw);
    k_topk<<<BB, 1024>>>();
    cudaEventRecord(eTopk, 0);

    cudaStreamWaitEvent(s2, eTopk, 0);
    k_pred2<<<NTOT/8, 256, 0, s2>>>(cfc2_w, cfc2_b);
    cudaEventRecord(ePred, s2);

    // fused gather + rmsnorm1
    k_grms<<<NTOK, 256>>>(hs, ln1, pA);

    cudaStreamWaitEvent(0, eQkv, 0);
    GEMM_S(0, pA, pB + OFF_QKV, NTOK, QSTR, HID, pqkvb, nullptr, (float*)pqkvh, 3);
    k_rope<<<(NTOK*NHEADS*64)/256, 256>>>();
    k_attn<<<dim3(KSEL/64, BB*NHEADS), 128, ATT_SMEM>>>(pA);

    cudaStreamWaitEvent(0, eO, 0);
    GEMM_S(0, pA, pB + OFF_O, NTOK, HID, HID, nullptr, px, ph1, 2);
    k_rms<<<NTOK, 256>>>(ph1, ln2, pA);

    // gate GEMM (fp32 pre-activation) then up GEMM with fused silu -> fp16
    cudaStreamWaitEvent(0, eGate, 0);
    GEMM_S(0, pA, pB + OFF_GATE, NTOK, INTER, HID, nullptr, nullptr, pgu, 0);
    cudaStreamWaitEvent(0, eUp, 0);
    GEMM_S(0, pA, pB + OFF_UP, NTOK, INTER, HID, nullptr, pgu, (float*)pqkvh, 6);

    // down-proj with fused residual + MoD scatter directly into out
    cudaStreamWaitEvent(0, eDown, 0);
    cudaStreamWaitEvent(0, eCopy, 0);
    GEMM_S(0, pqkvh, pB + OFF_DOWN, NTOK, HID, INTER, nullptr, ph1, out, 5);

    cudaStreamWaitEvent(0, ePred, 0);
    k_final<<<1, 32>>>(out, (long long)NTOT*HID, (long long)out_size);
}

// round 16
// speedup vs baseline: 1.0813x; 1.0813x over previous
#include <cuda_runtime.h>
#include <cuda_fp16.h>
#include <stdint.h>
#include <math.h>

#define BB     4
#define TT     4096
#define HID    2048
#define NHEADS 16
#define HDIM   128
#define INTER  8192
#define KSEL   512
#define NTOK   (BB*KSEL)
#define NTOT   (BB*TT)
#define CH     (HID/4)
#define QSTR   (3*HID)   // 6144

// B-buffer regions (halves)
#define OFF_CFC1 ((size_t)0)
#define OFF_QKV  ((size_t)CH*HID)
#define OFF_O    (OFF_QKV + (size_t)3*HID*HID)
#define OFF_GATE (OFF_O + (size_t)HID*HID)
#define OFF_UP   (OFF_GATE + (size_t)INTER*HID)
#define OFF_DOWN (OFF_UP + (size_t)INTER*HID)
#define B_TOTAL  (OFF_DOWN + (size_t)INTER*HID)

// ================= helpers =================
__device__ __forceinline__ uint32_t smem_to_u32(const void* p) {
    uint32_t a;
    asm("{ .reg .u64 t; cvta.to.shared.u64 t, %1; cvt.u32.u64 %0, t; }" : "=r"(a) : "l"(p));
    return a;
}
__device__ __forceinline__ void cp16(uint32_t s, const void* g) {
    asm volatile("cp.async.cg.shared.global [%0], [%1], 16;" :: "r"(s), "l"(g));
}
__device__ __forceinline__ void ldsm_x4(uint32_t* r, uint32_t addr) {
    asm volatile("ldmatrix.sync.aligned.m8n8.x4.shared.b16 {%0,%1,%2,%3}, [%4];"
        : "=r"(r[0]), "=r"(r[1]), "=r"(r[2]), "=r"(r[3]) : "r"(addr));
}
__device__ __forceinline__ void ldsm_x4_t(uint32_t* r, uint32_t addr) {
    asm volatile("ldmatrix.sync.aligned.m8n8.x4.trans.shared.b16 {%0,%1,%2,%3}, [%4];"
        : "=r"(r[0]), "=r"(r[1]), "=r"(r[2]), "=r"(r[3]) : "r"(addr));
}
__device__ __forceinline__ void mma16816(float* d, const uint32_t* a, const uint32_t* b) {
    asm volatile(
        "mma.sync.aligned.m16n8k16.row.col.f32.f16.f16.f32 "
        "{%0,%1,%2,%3}, {%4,%5,%6,%7}, {%8,%9}, {%0,%1,%2,%3};"
        : "+f"(d[0]), "+f"(d[1]), "+f"(d[2]), "+f"(d[3])
        : "r"(a[0]), "r"(a[1]), "r"(a[2]), "r"(a[3]), "r"(b[0]), "r"(b[1]));
}
__device__ __forceinline__ uint32_t packh2(float a, float b) {
    __half2 p = __floats2half2_rn(a, b);
    return *(uint32_t*)&p;
}

// ================= device scratch =================
__device__ float g_logits[NTOT];
__device__ float g_flags[NTOT];
__device__ int   g_idx[BB*KSEL];
__device__ float g_gate[BB*KSEL];
__device__ float g_act[NTOT*CH];
__device__ float g_x [NTOK*HID];
__device__ float g_h1[NTOK*HID];
__device__ float g_gu[(size_t)NTOK*2*INTER];
__device__ float g_qkvb[QSTR];
__device__ double g_f0sum, g_selsum, g_predsum;
__device__ __half g_A [33554432];
__device__ __half g_Ap[33554432];
__device__ __half g_B [B_TOTAL];
__device__ __half g_qkvh[(size_t)NTOK*QSTR];

// ================= small kernels =================
__global__ void k_init() {
    int i = blockIdx.x*blockDim.x + threadIdx.x;
    if (i < NTOT) g_flags[i] = 0.f;
    if (i == 0) { g_f0sum = 0.0; g_selsum = 0.0; g_predsum = 0.0; }
}

__global__ void k_router(const float* __restrict__ hs, const float* __restrict__ rw) {
    int t = blockIdx.x;
    const float* row = hs + (size_t)t*HID;
    float s = 0.f;
    for (int i = threadIdx.x; i < HID; i += 256) s += row[i]*rw[i];
    __shared__ float red[256];
    red[threadIdx.x] = s; __syncthreads();
    for (int st = 128; st; st >>= 1) {
        if (threadIdx.x < st) red[threadIdx.x] += red[threadIdx.x+st];
        __syncthreads();
    }
    if (threadIdx.x == 0) {
        float l = red[0];
        g_logits[t] = l;
        float f0 = fmaxf(l, 0.f) + log1pf(expf(-fabsf(l)));
        atomicAdd(&g_f0sum, (double)f0);
    }
}

// ---- radix-select top-KSEL (exact; ties -> lowest index; idx emitted ascending) ----
__global__ void k_topk() {
    int b = blockIdx.x, tid = threadIdx.x;
    __shared__ uint32_t su[TT];
    __shared__ float    sf[TT];
    __shared__ int      hist[256];
    __shared__ int      scan[1024];
    __shared__ uint32_t s_prefix;
    __shared__ int      s_kneed;

    for (int i = tid; i < TT; i += 1024) {
        float x = g_logits[b*TT + i];
        uint32_t bits = __float_as_uint(x);
        uint32_t u = bits ^ ((bits & 0x80000000u) ? 0xFFFFFFFFu : 0x80000000u);
        su[i] = u; sf[i] = x;
    }
    __syncthreads();

    uint32_t prefix = 0; int kneed = KSEL;
    for (int pass = 0; pass < 4; ++pass) {
        int shift = 24 - pass*8;
        uint32_t pmask = (pass == 0) ? 0u : (0xFFFFFFFFu << (32 - pass*8));
        if (tid < 256) hist[tid] = 0;
        __syncthreads();
        for (int i = tid; i < TT; i += 1024) {
            uint32_t u = su[i];
            if ((u & pmask) == prefix) atomicAdd(&hist[(u >> shift) & 255], 1);
        }
        __syncthreads();
        if (tid == 0) {
            int cum = 0, bsel = 0;
            for (int bin = 255; bin >= 0; --bin) {
                int c = hist[bin];
                if (cum + c >= kneed) { bsel = bin; break; }
                cum += c;
            }
            s_prefix = prefix | ((uint32_t)bsel << shift);
            s_kneed = kneed - cum;
        }
        __syncthreads();
        prefix = s_prefix; kneed = s_kneed;
        __syncthreads();
    }
    const uint32_t uthr = prefix;

    int i0 = tid*4;
    bool gt4[4], eq4[4];
    int eqc = 0;
#pragma unroll
    for (int j = 0; j < 4; j++) {
        uint32_t u = su[i0 + j];
        gt4[j] = (u > uthr); eq4[j] = (u == uthr);
        eqc += eq4[j];
    }
    scan[tid] = eqc; __syncthreads();
    for (int off = 1; off < 1024; off <<= 1) {
        int v = scan[tid];
        int va = (tid >= off) ? scan[tid - off] : 0;
        __syncthreads();
        scan[tid] = v + va;
        __syncthreads();
    }
    int eqbase = scan[tid] - eqc;

    bool sel4[4];
    int selc = 0, myeq = 0;
#pragma unroll
    for (int j = 0; j < 4; j++) {
        bool s = gt4[j];
        if (eq4[j]) { if (eqbase + myeq < kneed) s = true; myeq++; }
        sel4[j] = s; selc += s;
    }
    __syncthreads();
    scan[tid] = selc; __syncthreads();
    for (int off = 1; off < 1024; off <<= 1) {
        int v = scan[tid];
        int va = (tid >= off) ? scan[tid - off] : 0;
        __syncthreads();
        scan[tid] = v + va;
        __syncthreads();
    }
    int pos = scan[tid] - selc;

    double lsum = 0.0;
#pragma unroll
    for (int j = 0; j < 4; j++) {
        if (sel4[j]) {
            int i = i0 + j;
            float val = sf[i];
            g_idx[b*KSEL + pos] = i;
            g_gate[b*KSEL + pos] = 1.f/(1.f + expf(-val));
            g_flags[b*TT + i] = 1.f;
            lsum += (double)val;
            pos++;
        }
    }
    if (lsum != 0.0) atomicAdd(&g_selsum, lsum);
}

__global__ void k_pred2(const float* __restrict__ w2, const float* __restrict__ b2) {
    int warp = threadIdx.x >> 5, lane = threadIdx.x & 31;
    int t = blockIdx.x*8 + warp;
    const float* a = g_act + (size_t)t*CH;
    float s = 0.f;
    for (int i = lane; i < CH; i += 32) s += a[i]*w2[i];
    for (int o = 16; o; o >>= 1) s += __shfl_xor_sync(0xffffffffu, s, o);
    __shared__ float ps[8];
    if (lane == 0) {
        float p = s + b2[0];
        float tg = g_flags[t];
        ps[warp] = fmaxf(p, 0.f) - p*tg + log1pf(expf(-fabsf(p)));
    }
    __syncthreads();
    if (threadIdx.x == 0) {
        float tot = 0.f;
        for (int i = 0; i < 8; i++) tot += ps[i];
        atomicAdd(&g_predsum, (double)tot);
    }
}

// fused gather + rmsnorm1
__global__ void k_grms(const float* __restrict__ hs, const float* __restrict__ w,
                       __half* __restrict__ ha) {
    int bj = blockIdx.x, b = bj >> 9;
    int t = g_idx[bj];
    const float* src = hs + ((size_t)b*TT + t)*HID;
    int i = threadIdx.x*8;
    float4 a = *(const float4*)(src+i), bb = *(const float4*)(src+i+4);
    *(float4*)(g_x + (size_t)bj*HID + i)   = a;
    *(float4*)(g_x + (size_t)bj*HID + i+4) = bb;
    float ss = a.x*a.x + a.y*a.y + a.z*a.z + a.w*a.w
             + bb.x*bb.x + bb.y*bb.y + bb.z*bb.z + bb.w*bb.w;
    __shared__ float red[256];
    red[threadIdx.x] = ss; __syncthreads();
    for (int st = 128; st; st >>= 1) {
        if (threadIdx.x < st) red[threadIdx.x] += red[threadIdx.x+st];
        __syncthreads();
    }
    float sc = 1.f/sqrtf(red[0]/(float)HID + 1e-6f);
    float4 w0 = *(const float4*)(w+i), w1 = *(const float4*)(w+i+4);
    float v[8] = {a.x*sc*w0.x, a.y*sc*w0.y, a.z*sc*w0.z, a.w*sc*w0.w,
                  bb.x*sc*w1.x, bb.y*sc*w1.y, bb.z*sc*w1.z, bb.w*sc*w1.w};
    unsigned short hv[8];
#pragma unroll
    for (int j = 0; j < 8; j++) {
        __half hb = __float2half_rn(v[j]);
        hv[j] = *(unsigned short*)&hb;
    }
    *(uint4*)(ha + (size_t)bj*HID + i) = *(uint4*)hv;
}

__global__ void k_rms(const float* __restrict__ in, const float* __restrict__ w,
                      __half* __restrict__ ha) {
    int row = blockIdx.x;
    const float* src = in + (size_t)row*HID;
    int i = threadIdx.x*8;
    float4 a = *(const float4*)(src+i), b = *(const float4*)(src+i+4);
    float ss = a.x*a.x + a.y*a.y + a.z*a.z + a.w*a.w
             + b.x*b.x + b.y*b.y + b.z*b.z + b.w*b.w;
    __shared__ float red[256];
    red[threadIdx.x] = ss; __syncthreads();
    for (int st = 128; st; st >>= 1) {
        if (threadIdx.x < st) red[threadIdx.x] += red[threadIdx.x+st];
        __syncthreads();
    }
    float sc = 1.f/sqrtf(red[0]/(float)HID + 1e-6f);
    float4 w0 = *(const float4*)(w+i), w1 = *(const float4*)(w+i+4);
    float v[8] = {a.x*sc*w0.x, a.y*sc*w0.y, a.z*sc*w0.z, a.w*sc*w0.w,
                  b.x*sc*w1.x, b.y*sc*w1.y, b.z*sc*w1.z, b.w*sc*w1.w};
    unsigned short hv[8];
#pragma unroll
    for (int j = 0; j < 8; j++) {
        __half hb = __float2half_rn(v[j]);
        hv[j] = *(unsigned short*)&hb;
    }
    *(uint4*)(ha + (size_t)row*HID + i) = *(uint4*)hv;
}

__global__ void k_catbias(const float* __restrict__ qb, const float* __restrict__ kb,
                          const float* __restrict__ vb) {
    int i = blockIdx.x*256 + threadIdx.x;
    float v = (i < HID) ? qb[i] : (i < 2*HID ? kb[i-HID] : vb[i-2*HID]);
    g_qkvb[i] = v;
}

__global__ void k_rope() {
    int t = blockIdx.x*256 + threadIdx.x;
    int d = t & 63;
    int bh = t >> 6;
    int bj = bh >> 4, h = bh & 15;
    int pos = g_idx[bj];
    float ang = (float)pos * expf(-(float)d * 0.14391156831212787f);
    float c = cosf(ang), s = sinf(ang);
    size_t base = (size_t)bj*QSTR + h*HDIM;
    float q1 = __half2float(g_qkvh[base+d]), q2 = __half2float(g_qkvh[base+d+64]);
    g_qkvh[base+d]    = __float2half_rn(q1*c - q2*s);
    g_qkvh[base+d+64] = __float2half_rn(q2*c + q1*s);
    size_t kb = base + HID;
    float k1 = __half2float(g_qkvh[kb+d]), k2 = __half2float(g_qkvh[kb+d+64]);
    g_qkvh[kb+d]    = __float2half_rn(k1*c - k2*s);
    g_qkvh[kb+d+64] = __float2half_rn(k2*c + k1*s);
}

// ============== tensor-core flash attention ==============
#define PADQ 136
#define ATT_TB (64*PADQ*2)
#define ATT_SMEM (3*ATT_TB)

__device__ __forceinline__ void att_load_tile(uint32_t sdst, const __half* gsrc, int tid) {
#pragma unroll
    for (int u = 0; u < 8; u++) {
        int c = tid + u*128;
        int row = c >> 4, seg = (c & 15) << 3;
        cp16(sdst + (uint32_t)(row*PADQ + seg)*2, gsrc + (size_t)row*QSTR + seg);
    }
}

__global__ void __launch_bounds__(128, 1) k_attn(__half* __restrict__ oa) {
    extern __shared__ char smem[];
    uint32_t sb = smem_to_u32(smem);
    int qt = blockIdx.x, bh = blockIdx.y;
    int b = bh >> 4, h = bh & 15;
    int tid = threadIdx.x, w = tid >> 5, lane = tid & 31;

    const __half* qbase = g_qkvh + ((size_t)(b*KSEL + qt*64))*QSTR + h*HDIM;
    att_load_tile(sb, qbase, tid);
    asm volatile("cp.async.commit_group;" ::: "memory");
    asm volatile("cp.async.wait_group 0;" ::: "memory");
    __syncthreads();

    uint32_t Aq[8][4];
    {
        int arow = w*16 + (lane & 15);
        int acol = (lane >> 4) << 3;
#pragma unroll
        for (int ks = 0; ks < 8; ks++)
            ldsm_x4(Aq[ks], sb + (uint32_t)(arow*PADQ + ks*16 + acol)*2);
    }

    float co[16][4];
#pragma unroll
    for (int nt = 0; nt < 16; nt++)
#pragma unroll
        for (int i = 0; i < 4; i++) co[nt][i] = 0.f;
    float m0 = -1e30f, m1 = -1e30f, l0 = 0.f, l1 = 0.f;

    for (int kt = 0; kt <= qt; ++kt) {
        const __half* kbp = g_qkvh + ((size_t)(b*KSEL + kt*64))*QSTR + HID + h*HDIM;
        const __half* vbp = kbp + HID;
        __syncthreads();
        att_load_tile(sb + ATT_TB,   kbp, tid);
        att_load_tile(sb + 2*ATT_TB, vbp, tid);
        asm volatile("cp.async.commit_group;" ::: "memory");
        asm volatile("cp.async.wait_group 0;" ::: "memory");
        __syncthreads();

        float s[8][4];
#pragma unroll
        for (int nt = 0; nt < 8; nt++)
#pragma unroll
            for (int i = 0; i < 4; i++) s[nt][i] = 0.f;
        {
            int krow0 = (lane & 7) + ((lane >> 4) & 1)*8;
            int kcol0 = ((lane >> 3) & 1) << 3;
#pragma unroll
            for (int ks = 0; ks < 8; ks++) {
#pragma unroll
                for (int np = 0; np < 4; np++) {
                    uint32_t Kf[4];
                    ldsm_x4(Kf, sb + ATT_TB +
                        (uint32_t)((np*16 + krow0)*PADQ + ks*16 + kcol0)*2);
                    mma16816(s[2*np],   Aq[ks], Kf);
                    mma16816(s[2*np+1], Aq[ks], Kf+2);
                }
            }
        }
        const float SC = 0.08838834764831845f;
#pragma unroll
        for (int nt = 0; nt < 8; nt++)
#pragma unroll
            for (int i = 0; i < 4; i++) s[nt][i] *= SC;
        if (kt == qt) {
            int rq = w*16 + (lane >> 2);
#pragma unroll
            for (int nt = 0; nt < 8; nt++) {
                int j0 = nt*8 + 2*(lane & 3);
                if (j0   > rq)   s[nt][0] = -1e9f;
                if (j0+1 > rq)   s[nt][1] = -1e9f;
                if (j0   > rq+8) s[nt][2] = -1e9f;
                if (j0+1 > rq+8) s[nt][3] = -1e9f;
            }
        }
        float mx0 = -1e30f, mx1 = -1e30f;
#pragma unroll
        for (int nt = 0; nt < 8; nt++) {
            mx0 = fmaxf(mx0, fmaxf(s[nt][0], s[nt][1]));
            mx1 = fmaxf(mx1, fmaxf(s[nt][2], s[nt][3]));
        }
        mx0 = fmaxf(mx0, __shfl_xor_sync(0xffffffffu, mx0, 1));
        mx0 = fmaxf(mx0, __shfl_xor_sync(0xffffffffu, mx0, 2));
        mx1 = fmaxf(mx1, __shfl_xor_sync(0xffffffffu, mx1, 1));
        mx1 = fmaxf(mx1, __shfl_xor_sync(0xffffffffu, mx1, 2));
        float mn0 = fmaxf(m0, mx0), mn1 = fmaxf(m1, mx1);
        float c0 = __expf(m0 - mn0), c1 = __expf(m1 - mn1);
        float ls0 = 0.f, ls1 = 0.f;
#pragma unroll
        for (int nt = 0; nt < 8; nt++) {
            s[nt][0] = __expf(s[nt][0] - mn0); ls0 += s[nt][0];
            s[nt][1] = __expf(s[nt][1] - mn0); ls0 += s[nt][1];
            s[nt][2] = __expf(s[nt][2] - mn1); ls1 += s[nt][2];
            s[nt][3] = __expf(s[nt][3] - mn1); ls1 += s[nt][3];
        }
        ls0 += __shfl_xor_sync(0xffffffffu, ls0, 1);
        ls0 += __shfl_xor_sync(0xffffffffu, ls0, 2);
        ls1 += __shfl_xor_sync(0xffffffffu, ls1, 1);
        ls1 += __shfl_xor_sync(0xffffffffu, ls1, 2);
        l0 = l0*c0 + ls0; m0 = mn0;
        l1 = l1*c1 + ls1; m1 = mn1;
#pragma unroll
        for (int nt = 0; nt < 16; nt++) {
            co[nt][0] *= c0; co[nt][1] *= c0;
            co[nt][2] *= c1; co[nt][3] *= c1;
        }
        uint32_t Ap[4][4];
#pragma unroll
        for (int p = 0; p < 4; p++) {
            Ap[p][0] = packh2(s[2*p][0],   s[2*p][1]);
            Ap[p][1] = packh2(s[2*p][2],   s[2*p][3]);
            Ap[p][2] = packh2(s[2*p+1][0], s[2*p+1][1]);
            Ap[p][3] = packh2(s[2*p+1][2], s[2*p+1][3]);
        }
        {
            int vrow0 = lane & 15;
            int vcol0 = (lane >> 4) << 3;
#pragma unroll
            for (int ksj = 0; ksj < 4; ksj++) {
#pragma unroll
                for (int dc = 0; dc < 8; dc++) {
                    uint32_t Vf[4];
                    ldsm_x4_t(Vf, sb + 2*ATT_TB +
                        (uint32_t)((ksj*16 + vrow0)*PADQ + dc*16 + vcol0)*2);
                    mma16816(co[2*dc],   Ap[ksj], Vf);
                    mma16816(co[2*dc+1], Ap[ksj], Vf+2);
                }
            }
        }
    }
    float i0 = 1.f/l0, i1 = 1.f/l1;
    int r0 = qt*64 + w*16 + (lane >> 2);
    __half* ob = oa + ((size_t)(b*KSEL))*HID + h*HDIM;
#pragma unroll
    for (int nt = 0; nt < 16; nt++) {
        int d = nt*8 + 2*(lane & 3);
        *(uint32_t*)(ob + (size_t)r0*HID + d)     = packh2(co[nt][0]*i0, co[nt][1]*i0);
        *(uint32_t*)(ob + (size_t)(r0+8)*HID + d) = packh2(co[nt][2]*i1, co[nt][3]*i1);
    }
}

// silu(gate)*up from g_gu -> fp16 A operand
__global__ void k_silumul(__half* __restrict__ ha) {
    size_t idx = ((size_t)blockIdx.x*256 + threadIdx.x)*8;
    int m = (int)(idx >> 13);
    int n = (int)(idx & (INTER-1));
    const float* gp = g_gu + (size_t)m*(2*INTER) + n;
    const float* up = gp + INTER;
    float4 g0 = *(const float4*)gp,     g1 = *(const float4*)(gp+4);
    float4 u0 = *(const float4*)up,     u1 = *(const float4*)(up+4);
    float v[8] = {
        g0.x/(1.f+__expf(-g0.x))*u0.x, g0.y/(1.f+__expf(-g0.y))*u0.y,
        g0.z/(1.f+__expf(-g0.z))*u0.z, g0.w/(1.f+__expf(-g0.w))*u0.w,
        g1.x/(1.f+__expf(-g1.x))*u1.x, g1.y/(1.f+__expf(-g1.y))*u1.y,
        g1.z/(1.f+__expf(-g1.z))*u1.z, g1.w/(1.f+__expf(-g1.w))*u1.w };
    unsigned short hv[8];
#pragma unroll
    for (int j = 0; j < 8; j++) {
        __half hb = __float2half_rn(v[j]);
        hv[j] = *(unsigned short*)&hb;
    }
    *(uint4*)(ha + (size_t)m*INTER + n) = *(uint4*)hv;
}

__global__ void k_copy(const float* __restrict__ src, float* __restrict__ dst) {
    size_t i = ((size_t)blockIdx.x*256 + threadIdx.x)*4;
    *(float4*)(dst+i) = *(const float4*)(src+i);
}

__global__ void k_final(float* out, long long N, long long out_size) {
    if (threadIdx.x == 0) {
        if (N   < out_size) out[N]   = (float)((g_f0sum - g_selsum)/(double)NTOT);
        if (N+1 < out_size) out[N+1] = (float)(g_predsum/(double)NTOT);
    }
}

// ======== fp32 -> fp16 cast ========
__global__ void k_convB(const float* __restrict__ src, __half* __restrict__ dst) {
    size_t base = ((size_t)blockIdx.x*256 + threadIdx.x)*8;
    const float4* s = (const float4*)(src + base);
    float4 x0 = s[0], x1 = s[1];
    float xs[8] = {x0.x, x0.y, x0.z, x0.w, x1.x, x1.y, x1.z, x1.w};
    unsigned short hv[8];
#pragma unroll
    for (int j = 0; j < 8; j++) {
        __half hb = __float2half_rn(xs[j]);
        hv[j] = *(unsigned short*)&hb;
    }
    *(uint4*)(dst + base) = *(uint4*)hv;
}

// ================= fp16 MMA GEMM =================
// epi: 0 +bias(if set); 1 gelu(acc+bias); 2 acc+add; 3 +bias write fp16;
//      5 mod-scatter: out[b,idx[m]] = x + gate*((acc+add) - x)
#define PADK 40
#define A_BYTES   (128*PADK*2)
#define B_BYTES   (256*PADK*2)
#define STAGE_BYTES (A_BYTES + B_BYTES)
#define GEMM_SMEM (3*STAGE_BYTES)

__device__ __forceinline__ void load_stage(uint32_t sb, int stage,
    const __half* A, const __half* B, int K, int kt, int tid)
{
    uint32_t s0 = sb + stage*STAGE_BYTES;
#pragma unroll
    for (int u = 0; u < 2; u++) {
        int c = tid + u*256;
        int row = c >> 2, seg = (c & 3) << 3;
        cp16(s0 + (row*PADK + seg)*2, A + (size_t)row*K + (size_t)kt*32 + seg);
    }
#pragma unroll
    for (int u = 0; u < 4; u++) {
        int c = tid + u*256;
        int row = c >> 2, seg = (c & 3) << 3;
        cp16(s0 + A_BYTES + (row*PADK + seg)*2, B + (size_t)row*K + (size_t)kt*32 + seg);
    }
    asm volatile("cp.async.commit_group;" ::: "memory");
}

__global__ void __launch_bounds__(256, 1) tc_gemm(
    const __half* __restrict__ Ag, const __half* __restrict__ Bg,
    const float* __restrict__ bias, const float* __restrict__ add,
    float* __restrict__ C, int M, int N, int K, int epi)
{
    extern __shared__ __align__(16) char smem[];
    uint32_t sb = smem_to_u32(smem);
    const int tid = threadIdx.x, wid = tid >> 5, lane = tid & 31;
    const int wm = wid & 1, wn = wid >> 1;
    const long bm = (long)blockIdx.y << 7, bn = (long)blockIdx.x << 8;

    const __half* pA = Ag + (size_t)bm*K;
    const __half* pB = Bg + (size_t)bn*K;

    float acc[4][8][4];
#pragma unroll
    for (int mt = 0; mt < 4; mt++)
#pragma unroll
        for (int nt = 0; nt < 8; nt++)
#pragma unroll
            for (int i = 0; i < 4; i++) acc[mt][nt][i] = 0.f;

    const int NK = K >> 5;
    load_stage(sb, 0, pA, pB, K, 0, tid);
    load_stage(sb, 1, pA, pB, K, 1, tid);

    for (int kt = 0; kt < NK; ++kt) {
        if (kt + 2 < NK) {
            load_stage(sb, (kt+2)%3, pA, pB, K, kt+2, tid);
            asm volatile("cp.async.wait_group 2;" ::: "memory");
        } else {
            asm volatile("cp.async.wait_group 0;" ::: "memory");
        }
        __syncthreads();

        uint32_t s0 = sb + (kt%3)*STAGE_BYTES;
#pragma unroll
        for (int kk = 0; kk < 32; kk += 16) {
            uint32_t Af[4][4];
            const int arow = wm*64 + (lane & 15);
            const int acol = kk + ((lane >> 4) << 3);
#pragma unroll
            for (int mt = 0; mt < 4; mt++)
                ldsm_x4(Af[mt], s0 + (uint32_t)((arow + mt*16)*PADK + acol)*2);
            const int brow = wn*64 + (lane & 7) + (((lane >> 4) & 1) << 3);
            const int bcol = kk + (((lane >> 3) & 1) << 3);
#pragma unroll
            for (int np = 0; np < 4; np++) {
                uint32_t Bf[4];
                ldsm_x4(Bf, s0 + A_BYTES + (uint32_t)((brow + np*16)*PADK + bcol)*2);
#pragma unroll
                for (int mt = 0; mt < 4; mt++) {
                    mma16816(acc[mt][np*2],   Af[mt], Bf);
                    mma16816(acc[mt][np*2+1], Af[mt], Bf+2);
                }
            }
        }
        __syncthreads();
    }

#pragma unroll
    for (int mt = 0; mt < 4; mt++) {
#pragma unroll
        for (int nt = 0; nt < 8; nt++) {
            long m = bm + wm*64 + mt*16 + (lane >> 2);
            long n = bn + wn*64 + nt*8 + ((lane & 3) << 1);
            float* a = acc[mt][nt];
            float b0 = bias ? bias[n] : 0.f;
            float b1 = bias ? bias[n+1] : 0.f;
            float v0 = a[0] + b0, v1 = a[1] + b1, v2 = a[2] + b0, v3 = a[3] + b1;
            if (epi == 1) {
                v0 = 0.5f*v0*(1.f + erff(v0*0.70710678118654752f));
                v1 = 0.5f*v1*(1.f + erff(v1*0.70710678118654752f));
                v2 = 0.5f*v2*(1.f + erff(v2*0.70710678118654752f));
                v3 = 0.5f*v3*(1.f + erff(v3*0.70710678118654752f));
            }
            if (epi == 2) {
                v0 += add[m*N + n];     v1 += add[m*N + n + 1];
                v2 += add[(m+8)*N + n]; v3 += add[(m+8)*N + n + 1];
            }
            if (epi == 3) {
                __half* Ch = (__half*)C;
                *(uint32_t*)(Ch + m*(size_t)N + n)     = packh2(v0, v1);
                *(uint32_t*)(Ch + (m+8)*(size_t)N + n) = packh2(v2, v3);
            } else if (epi == 5) {
                long m2 = m + 8;
                float h0 = add[m*N + n],  h1v = add[m*N + n + 1];
                float h2 = add[m2*N + n], h3v = add[m2*N + n + 1];
                float x0v = g_x[m*N + n],  x1v = g_x[m*N + n + 1];
                float x2v = g_x[m2*N + n], x3v = g_x[m2*N + n + 1];
                float gt0 = g_gate[m], gt1 = g_gate[m2];
                long b0i = m >> 9,  t0 = g_idx[m];
                long b1i = m2 >> 9, t1 = g_idx[m2];
                float o0 = x0v + gt0*((v0 + h0)  - x0v);
                float o1 = x1v + gt0*((v1 + h1v) - x1v);
                float o2 = x2v + gt1*((v2 + h2)  - x2v);
                float o3 = x3v + gt1*((v3 + h3v) - x3v);
                *(float2*)(C + (b0i*TT + t0)*(long)HID + n) = make_float2(o0, o1);
                *(float2*)(C + (b1i*TT + t1)*(long)HID + n) = make_float2(o2, o3);
            } else {
                *(float2*)(C + m*N + n)     = make_float2(v0, v1);
                *(float2*)(C + (m+8)*N + n) = make_float2(v2, v3);
            }
        }
    }
}

// ================= launch =================
extern "C" void kernel_launch(void* const* d_in, const int* in_sizes, int n_in,
                              void* d_out, int out_size) {
    const float* hs     = (const float*)d_in[0];
    const float* rw     = (const float*)d_in[1];
    const float* cfc1_w = (const float*)d_in[2];
    const float* cfc1_b = (const float*)d_in[3];
    const float* cfc2_w = (const float*)d_in[4];
    const float* cfc2_b = (const float*)d_in[5];
    const float* ln1    = (const float*)d_in[6];
    const float* ln2    = (const float*)d_in[7];
    const float* q_w    = (const float*)d_in[8];
    const float* q_b    = (const float*)d_in[9];
    const float* k_w    = (const float*)d_in[10];
    const float* k_b    = (const float*)d_in[11];
    const float* v_w    = (const float*)d_in[12];
    const float* v_b    = (const float*)d_in[13];
    const float* o_w    = (const float*)d_in[14];
    const float* gate_w = (const float*)d_in[15];
    const float* up_w   = (const float*)d_in[16];
    const float* down_w = (const float*)d_in[17];
    float* out = (float*)d_out;

    float *px, *ph1, *pgu, *pact, *pqkvb;
    cudaGetSymbolAddress((void**)&px,  g_x);
    cudaGetSymbolAddress((void**)&ph1, g_h1);
    cudaGetSymbolAddress((void**)&pgu, g_gu);
    cudaGetSymbolAddress((void**)&pact, g_act);
    cudaGetSymbolAddress((void**)&pqkvb, g_qkvb);
    __half *pA, *pAp, *pB, *pqkvh;
    cudaGetSymbolAddress((void**)&pA,  g_A);
    cudaGetSymbolAddress((void**)&pAp, g_Ap);
    cudaGetSymbolAddress((void**)&pB,  g_B);
    cudaGetSymbolAddress((void**)&pqkvh, g_qkvh);

    cudaFuncSetAttribute(tc_gemm, cudaFuncAttributeMaxDynamicSharedMemorySize, GEMM_SMEM);
    cudaFuncSetAttribute(k_attn, cudaFuncAttributeMaxDynamicSharedMemorySize, ATT_SMEM);

    static bool s_init = false;
    static cudaStream_t s1, s2, s3;
    static cudaEvent_t e0, eTopk, eCfc1, eQkv, eO, eGU, eDown, eCopy, ePred;
    if (!s_init) {
        cudaStreamCreate(&s1); cudaStreamCreate(&s2); cudaStreamCreate(&s3);
        cudaEventCreateWithFlags(&e0,    cudaEventDisableTiming);
        cudaEventCreateWithFlags(&eTopk, cudaEventDisableTiming);
        cudaEventCreateWithFlags(&eCfc1, cudaEventDisableTiming);
        cudaEventCreateWithFlags(&eQkv,  cudaEventDisableTiming);
        cudaEventCreateWithFlags(&eO,    cudaEventDisableTiming);
        cudaEventCreateWithFlags(&eGU,   cudaEventDisableTiming);
        cudaEventCreateWithFlags(&eDown, cudaEventDisableTiming);
        cudaEventCreateWithFlags(&eCopy, cudaEventDisableTiming);
        cudaEventCreateWithFlags(&ePred, cudaEventDisableTiming);
        s_init = true;
    }

#define CONVB_S(st, src, dst, R, K) k_convB<<<((size_t)(R)*(K)/8)/256, 256, 0, st>>>(src, dst)
#define GEMM_S(st, Ap_, Bp_, M, N, K, bias, add, Cp, epi) \
    tc_gemm<<<dim3((N)/256, (M)/128), 256, GEMM_SMEM, st>>>(Ap_, Bp_, bias, add, Cp, M, N, K, epi)

    // ---- fork ----
    k_init<<<64, 256>>>();
    cudaEventRecord(e0, 0);
    cudaStreamWaitEvent(s1, e0, 0);
    cudaStreamWaitEvent(s2, e0, 0);
    cudaStreamWaitEvent(s3, e0, 0);

    // s1: weight conversions
    CONVB_S(s1, cfc1_w, pB + OFF_CFC1, CH, HID);
    cudaEventRecord(eCfc1, s1);
    CONVB_S(s1, q_w, pB + OFF_QKV,                     HID, HID);
    CONVB_S(s1, k_w, pB + OFF_QKV + (size_t)HID*HID,   HID, HID);
    CONVB_S(s1, v_w, pB + OFF_QKV + (size_t)2*HID*HID, HID, HID);
    k_catbias<<<QSTR/256, 256, 0, s1>>>(q_b, k_b, v_b);
    cudaEventRecord(eQkv, s1);
    CONVB_S(s1, o_w, pB + OFF_O, HID, HID);
    cudaEventRecord(eO, s1);
    CONVB_S(s1, gate_w, pB + OFF_GATE, INTER, HID);
    CONVB_S(s1, up_w,   pB + OFF_UP,   INTER, HID);
    cudaEventRecord(eGU, s1);
    CONVB_S(s1, down_w, pB + OFF_DOWN, HID, INTER);
    cudaEventRecord(eDown, s1);

    // s2: predictor chain
    CONVB_S(s2, hs, pAp, NTOT, HID);
    cudaStreamWaitEvent(s2, eCfc1, 0);
    GEMM_S(s2, pAp, pB + OFF_CFC1, NTOT, CH, HID, cfc1_b, nullptr, pact, 1);

    // s3: bulk output copy
    k_copy<<<((size_t)NTOT*HID/4)/256, 256, 0, s3>>>(hs, out);
    cudaEventRecord(eCopy, s3);

    // main: router -> radix topk -> attention block -> MLP
    k_router<<<NTOT, 256>>>(hs, rw);
    k_topk<<<BB, 1024>>>();
    cudaEventRecord(eTopk, 0);

    cudaStreamWaitEvent(s2, eTopk, 0);
    k_pred2<<<NTOT/8, 256, 0, s2>>>(cfc2_w, cfc2_b);
    cudaEventRecord(ePred, s2);

    // fused gather + rmsnorm1
    k_grms<<<NTOK, 256>>>(hs, ln1, pA);

    cudaStreamWaitEvent(0, eQkv, 0);
    GEMM_S(0, pA, pB + OFF_QKV, NTOK, QSTR, HID, pqkvb, nullptr, (float*)pqkvh, 3);
    k_rope<<<(NTOK*NHEADS*64)/256, 256>>>();
    k_attn<<<dim3(KSEL/64, BB*NHEADS), 128, ATT_SMEM>>>(pA);

    cudaStreamWaitEvent(0, eO, 0);
    GEMM_S(0, pA, pB + OFF_O, NTOK, HID, HID, nullptr, px, ph1, 2);
    k_rms<<<NTOK, 256>>>(ph1, ln2, pA);

    cudaStreamWaitEvent(0, eGU, 0);
    GEMM_S(0, pA, pB + OFF_GATE, NTOK, 2*INTER, HID, nullptr, nullptr, pgu, 0);
    k_silumul<<<(NTOK*(INTER/8))/256, 256>>>(pA);

    // down-proj with fused residual + MoD scatter directly into out
    cudaStreamWaitEvent(0, eDown, 0);
    cudaStreamWaitEvent(0, eCopy, 0);
    GEMM_S(0, pA, pB + OFF_DOWN, NTOK, HID, INTER, nullptr, ph1, out, 5);

    cudaStreamWaitEvent(0, ePred, 0);
    k_final<<<1, 32>>>(out, (long long)NTOT*HID, (long long)out_size);
}

// round 17
// speedup vs baseline: 1.0814x; 1.0001x over previous
#include <cuda_runtime.h>
#include <cuda_fp16.h>
#include <stdint.h>
#include <math.h>

#define BB     4
#define TT     4096
#define HID    2048
#define NHEADS 16
#define HDIM   128
#define INTER  8192
#define KSEL   512
#define NTOK   (BB*KSEL)
#define NTOT   (BB*TT)
#define CH     (HID/4)
#define QSTR   (3*HID)   // 6144

// B-buffer regions (halves)
#define OFF_CFC1 ((size_t)0)
#define OFF_QKV  ((size_t)CH*HID)
#define OFF_O    (OFF_QKV + (size_t)3*HID*HID)
#define OFF_GATE (OFF_O + (size_t)HID*HID)
#define OFF_UP   (OFF_GATE + (size_t)INTER*HID)
#define OFF_DOWN (OFF_UP + (size_t)INTER*HID)
#define B_TOTAL  (OFF_DOWN + (size_t)INTER*HID)

// ================= helpers =================
__device__ __forceinline__ uint32_t smem_to_u32(const void* p) {
    uint32_t a;
    asm("{ .reg .u64 t; cvta.to.shared.u64 t, %1; cvt.u32.u64 %0, t; }" : "=r"(a) : "l"(p));
    return a;
}
__device__ __forceinline__ void cp16(uint32_t s, const void* g) {
    asm volatile("cp.async.cg.shared.global [%0], [%1], 16;" :: "r"(s), "l"(g));
}
__device__ __forceinline__ void ldsm_x4(uint32_t* r, uint32_t addr) {
    asm volatile("ldmatrix.sync.aligned.m8n8.x4.shared.b16 {%0,%1,%2,%3}, [%4];"
        : "=r"(r[0]), "=r"(r[1]), "=r"(r[2]), "=r"(r[3]) : "r"(addr));
}
__device__ __forceinline__ void ldsm_x4_t(uint32_t* r, uint32_t addr) {
    asm volatile("ldmatrix.sync.aligned.m8n8.x4.trans.shared.b16 {%0,%1,%2,%3}, [%4];"
        : "=r"(r[0]), "=r"(r[1]), "=r"(r[2]), "=r"(r[3]) : "r"(addr));
}
__device__ __forceinline__ void mma16816(float* d, const uint32_t* a, const uint32_t* b) {
    asm volatile(
        "mma.sync.aligned.m16n8k16.row.col.f32.f16.f16.f32 "
        "{%0,%1,%2,%3}, {%4,%5,%6,%7}, {%8,%9}, {%0,%1,%2,%3};"
        : "+f"(d[0]), "+f"(d[1]), "+f"(d[2]), "+f"(d[3])
        : "r"(a[0]), "r"(a[1]), "r"(a[2]), "r"(a[3]), "r"(b[0]), "r"(b[1]));
}
__device__ __forceinline__ uint32_t packh2(float a, float b) {
    __half2 p = __floats2half2_rn(a, b);
    return *(uint32_t*)&p;
}

// ================= device scratch =================
__device__ float g_logits[NTOT];
__device__ float g_flags[NTOT];
__device__ int   g_idx[BB*KSEL];
__device__ float g_gate[BB*KSEL];
__device__ float g_act[NTOT*CH];
__device__ float g_x [NTOK*HID];
__device__ float g_h1[NTOK*HID];
__device__ float g_gu[(size_t)NTOK*2*INTER];
__device__ float g_qkvb[QSTR];
__device__ double g_f0sum, g_selsum, g_predsum;
__device__ __half g_A [33554432];
__device__ __half g_Ap[33554432];
__device__ __half g_B [B_TOTAL];
__device__ __half g_qkvh[(size_t)NTOK*QSTR];

// ================= small kernels =================
__global__ void k_init() {
    int i = blockIdx.x*blockDim.x + threadIdx.x;
    if (i < NTOT) g_flags[i] = 0.f;
    if (i == 0) { g_f0sum = 0.0; g_selsum = 0.0; g_predsum = 0.0; }
}

__global__ void k_router(const float* __restrict__ hs, const float* __restrict__ rw) {
    int t = blockIdx.x;
    const float* row = hs + (size_t)t*HID;
    float s = 0.f;
    for (int i = threadIdx.x; i < HID; i += 256) s += row[i]*rw[i];
    __shared__ float red[256];
    red[threadIdx.x] = s; __syncthreads();
    for (int st = 128; st; st >>= 1) {
        if (threadIdx.x < st) red[threadIdx.x] += red[threadIdx.x+st];
        __syncthreads();
    }
    if (threadIdx.x == 0) {
        float l = red[0];
        g_logits[t] = l;
        float f0 = fmaxf(l, 0.f) + log1pf(expf(-fabsf(l)));
        atomicAdd(&g_f0sum, (double)f0);
    }
}

// ---- radix-select top-KSEL (exact; ties -> lowest index; idx emitted ascending) ----
__global__ void k_topk() {
    int b = blockIdx.x, tid = threadIdx.x;
    __shared__ uint32_t su[TT];
    __shared__ float    sf[TT];
    __shared__ int      hist[256];
    __shared__ int      scan[1024];
    __shared__ uint32_t s_prefix;
    __shared__ int      s_kneed;

    for (int i = tid; i < TT; i += 1024) {
        float x = g_logits[b*TT + i];
        uint32_t bits = __float_as_uint(x);
        uint32_t u = bits ^ ((bits & 0x80000000u) ? 0xFFFFFFFFu : 0x80000000u);
        su[i] = u; sf[i] = x;
    }
    __syncthreads();

    uint32_t prefix = 0; int kneed = KSEL;
    for (int pass = 0; pass < 4; ++pass) {
        int shift = 24 - pass*8;
        uint32_t pmask = (pass == 0) ? 0u : (0xFFFFFFFFu << (32 - pass*8));
        if (tid < 256) hist[tid] = 0;
        __syncthreads();
        for (int i = tid; i < TT; i += 1024) {
            uint32_t u = su[i];
            if ((u & pmask) == prefix) atomicAdd(&hist[(u >> shift) & 255], 1);
        }
        __syncthreads();
        if (tid == 0) {
            int cum = 0, bsel = 0;
            for (int bin = 255; bin >= 0; --bin) {
                int c = hist[bin];
                if (cum + c >= kneed) { bsel = bin; break; }
                cum += c;
            }
            s_prefix = prefix | ((uint32_t)bsel << shift);
            s_kneed = kneed - cum;
        }
        __syncthreads();
        prefix = s_prefix; kneed = s_kneed;
        __syncthreads();
    }
    const uint32_t uthr = prefix;

    int i0 = tid*4;
    bool gt4[4], eq4[4];
    int eqc = 0;
#pragma unroll
    for (int j = 0; j < 4; j++) {
        uint32_t u = su[i0 + j];
        gt4[j] = (u > uthr); eq4[j] = (u == uthr);
        eqc += eq4[j];
    }
    scan[tid] = eqc; __syncthreads();
    for (int off = 1; off < 1024; off <<= 1) {
        int v = scan[tid];
        int va = (tid >= off) ? scan[tid - off] : 0;
        __syncthreads();
        scan[tid] = v + va;
        __syncthreads();
    }
    int eqbase = scan[tid] - eqc;

    bool sel4[4];
    int selc = 0, myeq = 0;
#pragma unroll
    for (int j = 0; j < 4; j++) {
        bool s = gt4[j];
        if (eq4[j]) { if (eqbase + myeq < kneed) s = true; myeq++; }
        sel4[j] = s; selc += s;
    }
    __syncthreads();
    scan[tid] = selc; __syncthreads();
    for (int off = 1; off < 1024; off <<= 1) {
        int v = scan[tid];
        int va = (tid >= off) ? scan[tid - off] : 0;
        __syncthreads();
        scan[tid] = v + va;
        __syncthreads();
    }
    int pos = scan[tid] - selc;

    double lsum = 0.0;
#pragma unroll
    for (int j = 0; j < 4; j++) {
        if (sel4[j]) {
            int i = i0 + j;
            float val = sf[i];
            g_idx[b*KSEL + pos] = i;
            g_gate[b*KSEL + pos] = 1.f/(1.f + expf(-val));
            g_flags[b*TT + i] = 1.f;
            lsum += (double)val;
            pos++;
        }
    }
    if (lsum != 0.0) atomicAdd(&g_selsum, lsum);
}

__global__ void k_pred2(const float* __restrict__ w2, const float* __restrict__ b2) {
    int warp = threadIdx.x >> 5, lane = threadIdx.x & 31;
    int t = blockIdx.x*8 + warp;
    const float* a = g_act + (size_t)t*CH;
    float s = 0.f;
    for (int i = lane; i < CH; i += 32) s += a[i]*w2[i];
    for (int o = 16; o; o >>= 1) s += __shfl_xor_sync(0xffffffffu, s, o);
    __shared__ float ps[8];
    if (lane == 0) {
        float p = s + b2[0];
        float tg = g_flags[t];
        ps[warp] = fmaxf(p, 0.f) - p*tg + log1pf(expf(-fabsf(p)));
    }
    __syncthreads();
    if (threadIdx.x == 0) {
        float tot = 0.f;
        for (int i = 0; i < 8; i++) tot += ps[i];
        atomicAdd(&g_predsum, (double)tot);
    }
}

// fused gather + rmsnorm1
__global__ void k_grms(const float* __restrict__ hs, const float* __restrict__ w,
                       __half* __restrict__ ha) {
    int bj = blockIdx.x, b = bj >> 9;
    int t = g_idx[bj];
    const float* src = hs + ((size_t)b*TT + t)*HID;
    int i = threadIdx.x*8;
    float4 a = *(const float4*)(src+i), bb = *(const float4*)(src+i+4);
    *(float4*)(g_x + (size_t)bj*HID + i)   = a;
    *(float4*)(g_x + (size_t)bj*HID + i+4) = bb;
    float ss = a.x*a.x + a.y*a.y + a.z*a.z + a.w*a.w
             + bb.x*bb.x + bb.y*bb.y + bb.z*bb.z + bb.w*bb.w;
    __shared__ float red[256];
    red[threadIdx.x] = ss; __syncthreads();
    for (int st = 128; st; st >>= 1) {
        if (threadIdx.x < st) red[threadIdx.x] += red[threadIdx.x+st];
        __syncthreads();
    }
    float sc = 1.f/sqrtf(red[0]/(float)HID + 1e-6f);
    float4 w0 = *(const float4*)(w+i), w1 = *(const float4*)(w+i+4);
    float v[8] = {a.x*sc*w0.x, a.y*sc*w0.y, a.z*sc*w0.z, a.w*sc*w0.w,
                  bb.x*sc*w1.x, bb.y*sc*w1.y, bb.z*sc*w1.z, bb.w*sc*w1.w};
    unsigned short hv[8];
#pragma unroll
    for (int j = 0; j < 8; j++) {
        __half hb = __float2half_rn(v[j]);
        hv[j] = *(unsigned short*)&hb;
    }
    *(uint4*)(ha + (size_t)bj*HID + i) = *(uint4*)hv;
}

__global__ void k_rms(const float* __restrict__ in, const float* __restrict__ w,
                      __half* __restrict__ ha) {
    int row = blockIdx.x;
    const float* src = in + (size_t)row*HID;
    int i = threadIdx.x*8;
    float4 a = *(const float4*)(src+i), b = *(const float4*)(src+i+4);
    float ss = a.x*a.x + a.y*a.y + a.z*a.z + a.w*a.w
             + b.x*b.x + b.y*b.y + b.z*b.z + b.w*b.w;
    __shared__ float red[256];
    red[threadIdx.x] = ss; __syncthreads();
    for (int st = 128; st; st >>= 1) {
        if (threadIdx.x < st) red[threadIdx.x] += red[threadIdx.x+st];
        __syncthreads();
    }
    float sc = 1.f/sqrtf(red[0]/(float)HID + 1e-6f);
    float4 w0 = *(const float4*)(w+i), w1 = *(const float4*)(w+i+4);
    float v[8] = {a.x*sc*w0.x, a.y*sc*w0.y, a.z*sc*w0.z, a.w*sc*w0.w,
                  b.x*sc*w1.x, b.y*sc*w1.y, b.z*sc*w1.z, b.w*sc*w1.w};
    unsigned short hv[8];
#pragma unroll
    for (int j = 0; j < 8; j++) {
        __half hb = __float2half_rn(v[j]);
        hv[j] = *(unsigned short*)&hb;
    }
    *(uint4*)(ha + (size_t)row*HID + i) = *(uint4*)hv;
}

__global__ void k_catbias(const float* __restrict__ qb, const float* __restrict__ kb,
                          const float* __restrict__ vb) {
    int i = blockIdx.x*256 + threadIdx.x;
    float v = (i < HID) ? qb[i] : (i < 2*HID ? kb[i-HID] : vb[i-2*HID]);
    g_qkvb[i] = v;
}

// rope: 2 adjacent d-values per thread, half2 I/O (numerics identical per element)
__global__ void k_rope() {
    int t = blockIdx.x*256 + threadIdx.x;   // [0, NTOK*NHEADS*32)
    int dp = (t & 31) << 1;                 // even d: 0,2,...,62
    int bh = t >> 5;
    int bj = bh >> 4, h = bh & 15;
    int pos = g_idx[bj];
    float a0 = (float)pos * expf(-(float)dp     * 0.14391156831212787f);
    float a1 = (float)pos * expf(-(float)(dp+1) * 0.14391156831212787f);
    float c0 = cosf(a0), s0 = sinf(a0);
    float c1 = cosf(a1), s1 = sinf(a1);
    size_t base = (size_t)bj*QSTR + h*HDIM;
    // q
    {
        __half2 lo = *(__half2*)(g_qkvh + base + dp);
        __half2 hi = *(__half2*)(g_qkvh + base + dp + 64);
        float q1x = __low2float(lo), q1y = __high2float(lo);
        float q2x = __low2float(hi), q2y = __high2float(hi);
        *(__half2*)(g_qkvh + base + dp)      = __floats2half2_rn(q1x*c0 - q2x*s0, q1y*c1 - q2y*s1);
        *(__half2*)(g_qkvh + base + dp + 64) = __floats2half2_rn(q2x*c0 + q1x*s0, q2y*c1 + q1y*s1);
    }
    // k
    {
        size_t kb = base + HID;
        __half2 lo = *(__half2*)(g_qkvh + kb + dp);
        __half2 hi = *(__half2*)(g_qkvh + kb + dp + 64);
        float k1x = __low2float(lo), k1y = __high2float(lo);
        float k2x = __low2float(hi), k2y = __high2float(hi);
        *(__half2*)(g_qkvh + kb + dp)      = __floats2half2_rn(k1x*c0 - k2x*s0, k1y*c1 - k2y*s1);
        *(__half2*)(g_qkvh + kb + dp + 64) = __floats2half2_rn(k2x*c0 + k1x*s0, k2y*c1 + k1y*s1);
    }
}

// ============== tensor-core flash attention ==============
#define PADQ 136
#define ATT_TB (64*PADQ*2)
#define ATT_SMEM (3*ATT_TB)

__device__ __forceinline__ void att_load_tile(uint32_t sdst, const __half* gsrc, int tid) {
#pragma unroll
    for (int u = 0; u < 8; u++) {
        int c = tid + u*128;
        int row = c >> 4, seg = (c & 15) << 3;
        cp16(sdst + (uint32_t)(row*PADQ + seg)*2, gsrc + (size_t)row*QSTR + seg);
    }
}

__global__ void __launch_bounds__(128, 1) k_attn(__half* __restrict__ oa) {
    extern __shared__ char smem[];
    uint32_t sb = smem_to_u32(smem);
    int qt = (int)gridDim.x - 1 - (int)blockIdx.x;   // heavy blocks first (LPT)
    int bh = blockIdx.y;
    int b = bh >> 4, h = bh & 15;
    int tid = threadIdx.x, w = tid >> 5, lane = tid & 31;

    const __half* qbase = g_qkvh + ((size_t)(b*KSEL + qt*64))*QSTR + h*HDIM;
    att_load_tile(sb, qbase, tid);
    asm volatile("cp.async.commit_group;" ::: "memory");
    asm volatile("cp.async.wait_group 0;" ::: "memory");
    __syncthreads();

    uint32_t Aq[8][4];
    {
        int arow = w*16 + (lane & 15);
        int acol = (lane >> 4) << 3;
#pragma unroll
        for (int ks = 0; ks < 8; ks++)
            ldsm_x4(Aq[ks], sb + (uint32_t)(arow*PADQ + ks*16 + acol)*2);
    }

    float co[16][4];
#pragma unroll
    for (int nt = 0; nt < 16; nt++)
#pragma unroll
        for (int i = 0; i < 4; i++) co[nt][i] = 0.f;
    float m0 = -1e30f, m1 = -1e30f, l0 = 0.f, l1 = 0.f;

    for (int kt = 0; kt <= qt; ++kt) {
        const __half* kbp = g_qkvh + ((size_t)(b*KSEL + kt*64))*QSTR + HID + h*HDIM;
        const __half* vbp = kbp + HID;
        __syncthreads();
        att_load_tile(sb + ATT_TB,   kbp, tid);
        att_load_tile(sb + 2*ATT_TB, vbp, tid);
        asm volatile("cp.async.commit_group;" ::: "memory");
        asm volatile("cp.async.wait_group 0;" ::: "memory");
        __syncthreads();

        float s[8][4];
#pragma unroll
        for (int nt = 0; nt < 8; nt++)
#pragma unroll
            for (int i = 0; i < 4; i++) s[nt][i] = 0.f;
        {
            int krow0 = (lane & 7) + ((lane >> 4) & 1)*8;
            int kcol0 = ((lane >> 3) & 1) << 3;
#pragma unroll
            for (int ks = 0; ks < 8; ks++) {
#pragma unroll
                for (int np = 0; np < 4; np++) {
                    uint32_t Kf[4];
                    ldsm_x4(Kf, sb + ATT_TB +
                        (uint32_t)((np*16 + krow0)*PADQ + ks*16 + kcol0)*2);
                    mma16816(s[2*np],   Aq[ks], Kf);
                    mma16816(s[2*np+1], Aq[ks], Kf+2);
                }
            }
        }
        const float SC = 0.08838834764831845f;
#pragma unroll
        for (int nt = 0; nt < 8; nt++)
#pragma unroll
            for (int i = 0; i < 4; i++) s[nt][i] *= SC;
        if (kt == qt) {
            int rq = w*16 + (lane >> 2);
#pragma unroll
            for (int nt = 0; nt < 8; nt++) {
                int j0 = nt*8 + 2*(lane & 3);
                if (j0   > rq)   s[nt][0] = -1e9f;
                if (j0+1 > rq)   s[nt][1] = -1e9f;
                if (j0   > rq+8) s[nt][2] = -1e9f;
                if (j0+1 > rq+8) s[nt][3] = -1e9f;
            }
        }
        float mx0 = -1e30f, mx1 = -1e30f;
#pragma unroll
        for (int nt = 0; nt < 8; nt++) {
            mx0 = fmaxf(mx0, fmaxf(s[nt][0], s[nt][1]));
            mx1 = fmaxf(mx1, fmaxf(s[nt][2], s[nt][3]));
        }
        mx0 = fmaxf(mx0, __shfl_xor_sync(0xffffffffu, mx0, 1));
        mx0 = fmaxf(mx0, __shfl_xor_sync(0xffffffffu, mx0, 2));
        mx1 = fmaxf(mx1, __shfl_xor_sync(0xffffffffu, mx1, 1));
        mx1 = fmaxf(mx1, __shfl_xor_sync(0xffffffffu, mx1, 2));
        float mn0 = fmaxf(m0, mx0), mn1 = fmaxf(m1, mx1);
        float c0 = __expf(m0 - mn0), c1 = __expf(m1 - mn1);
        float ls0 = 0.f, ls1 = 0.f;
#pragma unroll
        for (int nt = 0; nt < 8; nt++) {
            s[nt][0] = __expf(s[nt][0] - mn0); ls0 += s[nt][0];
            s[nt][1] = __expf(s[nt][1] - mn0); ls0 += s[nt][1];
            s[nt][2] = __expf(s[nt][2] - mn1); ls1 += s[nt][2];
            s[nt][3] = __expf(s[nt][3] - mn1); ls1 += s[nt][3];
        }
        ls0 += __shfl_xor_sync(0xffffffffu, ls0, 1);
        ls0 += __shfl_xor_sync(0xffffffffu, ls0, 2);
        ls1 += __shfl_xor_sync(0xffffffffu, ls1, 1);
        ls1 += __shfl_xor_sync(0xffffffffu, ls1, 2);
        l0 = l0*c0 + ls0; m0 = mn0;
        l1 = l1*c1 + ls1; m1 = mn1;
#pragma unroll
        for (int nt = 0; nt < 16; nt++) {
            co[nt][0] *= c0; co[nt][1] *= c0;
            co[nt][2] *= c1; co[nt][3] *= c1;
        }
        uint32_t Ap[4][4];
#pragma unroll
        for (int p = 0; p < 4; p++) {
            Ap[p][0] = packh2(s[2*p][0],   s[2*p][1]);
            Ap[p][1] = packh2(s[2*p][2],   s[2*p][3]);
            Ap[p][2] = packh2(s[2*p+1][0], s[2*p+1][1]);
            Ap[p][3] = packh2(s[2*p+1][2], s[2*p+1][3]);
        }
        {
            int vrow0 = lane & 15;
            int vcol0 = (lane >> 4) << 3;
#pragma unroll
            for (int ksj = 0; ksj < 4; ksj++) {
#pragma unroll
                for (int dc = 0; dc < 8; dc++) {
                    uint32_t Vf[4];
                    ldsm_x4_t(Vf, sb + 2*ATT_TB +
                        (uint32_t)((ksj*16 + vrow0)*PADQ + dc*16 + vcol0)*2);
                    mma16816(co[2*dc],   Ap[ksj], Vf);
                    mma16816(co[2*dc+1], Ap[ksj], Vf+2);
                }
            }
        }
    }
    float i0 = 1.f/l0, i1 = 1.f/l1;
    int r0 = qt*64 + w*16 + (lane >> 2);
    __half* ob = oa + ((size_t)(b*KSEL))*HID + h*HDIM;
#pragma unroll
    for (int nt = 0; nt < 16; nt++) {
        int d = nt*8 + 2*(lane & 3);
        *(uint32_t*)(ob + (size_t)r0*HID + d)     = packh2(co[nt][0]*i0, co[nt][1]*i0);
        *(uint32_t*)(ob + (size_t)(r0+8)*HID + d) = packh2(co[nt][2]*i1, co[nt][3]*i1);
    }
}

// silu(gate)*up from g_gu -> fp16 A operand
__global__ void k_silumul(__half* __restrict__ ha) {
    size_t idx = ((size_t)blockIdx.x*256 + threadIdx.x)*8;
    int m = (int)(idx >> 13);
    int n = (int)(idx & (INTER-1));
    const float* gp = g_gu + (size_t)m*(2*INTER) + n;
    const float* up = gp + INTER;
    float4 g0 = *(const float4*)gp,     g1 = *(const float4*)(gp+4);
    float4 u0 = *(const float4*)up,     u1 = *(const float4*)(up+4);
    float v[8] = {
        g0.x/(1.f+__expf(-g0.x))*u0.x, g0.y/(1.f+__expf(-g0.y))*u0.y,
        g0.z/(1.f+__expf(-g0.z))*u0.z, g0.w/(1.f+__expf(-g0.w))*u0.w,
        g1.x/(1.f+__expf(-g1.x))*u1.x, g1.y/(1.f+__expf(-g1.y))*u1.y,
        g1.z/(1.f+__expf(-g1.z))*u1.z, g1.w/(1.f+__expf(-g1.w))*u1.w };
    unsigned short hv[8];
#pragma unroll
    for (int j = 0; j < 8; j++) {
        __half hb = __float2half_rn(v[j]);
        hv[j] = *(unsigned short*)&hb;
    }
    *(uint4*)(ha + (size_t)m*INTER + n) = *(uint4*)hv;
}

__global__ void k_copy(const float* __restrict__ src, float* __restrict__ dst) {
    size_t i = ((size_t)blockIdx.x*256 + threadIdx.x)*4;
    *(float4*)(dst+i) = *(const float4*)(src+i);
}

__global__ void k_final(float* out, long long N, long long out_size) {
    if (threadIdx.x == 0) {
        if (N   < out_size) out[N]   = (float)((g_f0sum - g_selsum)/(double)NTOT);
        if (N+1 < out_size) out[N+1] = (float)(g_predsum/(double)NTOT);
    }
}

// ======== fp32 -> fp16 cast ========
__global__ void k_convB(const float* __restrict__ src, __half* __restrict__ dst) {
    size_t base = ((size_t)blockIdx.x*256 + threadIdx.x)*8;
    const float4* s = (const float4*)(src + base);
    float4 x0 = s[0], x1 = s[1];
    float xs[8] = {x0.x, x0.y, x0.z, x0.w, x1.x, x1.y, x1.z, x1.w};
    unsigned short hv[8];
#pragma unroll
    for (int j = 0; j < 8; j++) {
        __half hb = __float2half_rn(xs[j]);
        hv[j] = *(unsigned short*)&hb;
    }
    *(uint4*)(dst + base) = *(uint4*)hv;
}

// ================= fp16 MMA GEMM =================
// epi: 0 +bias(if set); 1 gelu(acc+bias); 2 acc+add; 3 +bias write fp16;
//      5 mod-scatter: out[b,idx[m]] = x + gate*((acc+add) - x)
#define PADK 40
#define A_BYTES   (128*PADK*2)
#define B_BYTES   (256*PADK*2)
#define STAGE_BYTES (A_BYTES + B_BYTES)
#define GEMM_SMEM (3*STAGE_BYTES)

__device__ __forceinline__ void load_stage(uint32_t sb, int stage,
    const __half* A, const __half* B, int K, int kt, int tid)
{
    uint32_t s0 = sb + stage*STAGE_BYTES;
#pragma unroll
    for (int u = 0; u < 2; u++) {
        int c = tid + u*256;
        int row = c >> 2, seg = (c & 3) << 3;
        cp16(s0 + (row*PADK + seg)*2, A + (size_t)row*K + (size_t)kt*32 + seg);
    }
#pragma unroll
    for (int u = 0; u < 4; u++) {
        int c = tid + u*256;
        int row = c >> 2, seg = (c & 3) << 3;
        cp16(s0 + A_BYTES + (row*PADK + seg)*2, B + (size_t)row*K + (size_t)kt*32 + seg);
    }
    asm volatile("cp.async.commit_group;" ::: "memory");
}

__global__ void __launch_bounds__(256, 1) tc_gemm(
    const __half* __restrict__ Ag, const __half* __restrict__ Bg,
    const float* __restrict__ bias, const float* __restrict__ add,
    float* __restrict__ C, int M, int N, int K, int epi)
{
    extern __shared__ __align__(16) char smem[];
    uint32_t sb = smem_to_u32(smem);
    const int tid = threadIdx.x, wid = tid >> 5, lane = tid & 31;
    const int wm = wid & 1, wn = wid >> 1;
    const long bm = (long)blockIdx.y << 7, bn = (long)blockIdx.x << 8;

    const __half* pA = Ag + (size_t)bm*K;
    const __half* pB = Bg + (size_t)bn*K;

    float acc[4][8][4];
#pragma unroll
    for (int mt = 0; mt < 4; mt++)
#pragma unroll
        for (int nt = 0; nt < 8; nt++)
#pragma unroll
            for (int i = 0; i < 4; i++) acc[mt][nt][i] = 0.f;

    const int NK = K >> 5;
    load_stage(sb, 0, pA, pB, K, 0, tid);
    load_stage(sb, 1, pA, pB, K, 1, tid);

    for (int kt = 0; kt < NK; ++kt) {
        if (kt + 2 < NK) {
            load_stage(sb, (kt+2)%3, pA, pB, K, kt+2, tid);
            asm volatile("cp.async.wait_group 2;" ::: "memory");
        } else {
            asm volatile("cp.async.wait_group 0;" ::: "memory");
        }
        __syncthreads();

        uint32_t s0 = sb + (kt%3)*STAGE_BYTES;
#pragma unroll
        for (int kk = 0; kk < 32; kk += 16) {
            uint32_t Af[4][4];
            const int arow = wm*64 + (lane & 15);
            const int acol = kk + ((lane >> 4) << 3);
#pragma unroll
            for (int mt = 0; mt < 4; mt++)
                ldsm_x4(Af[mt], s0 + (uint32_t)((arow + mt*16)*PADK + acol)*2);
            const int brow = wn*64 + (lane & 7) + (((lane >> 4) & 1) << 3);
            const int bcol = kk + (((lane >> 3) & 1) << 3);
#pragma unroll
            for (int np = 0; np < 4; np++) {
                uint32_t Bf[4];
                ldsm_x4(Bf, s0 + A_BYTES + (uint32_t)((brow + np*16)*PADK + bcol)*2);
#pragma unroll
                for (int mt = 0; mt < 4; mt++) {
                    mma16816(acc[mt][np*2],   Af[mt], Bf);
                    mma16816(acc[mt][np*2+1], Af[mt], Bf+2);
                }
            }
        }
        __syncthreads();
    }

#pragma unroll
    for (int mt = 0; mt < 4; mt++) {
#pragma unroll
        for (int nt = 0; nt < 8; nt++) {
            long m = bm + wm*64 + mt*16 + (lane >> 2);
            long n = bn + wn*64 + nt*8 + ((lane & 3) << 1);
            float* a = acc[mt][nt];
            float b0 = bias ? bias[n] : 0.f;
            float b1 = bias ? bias[n+1] : 0.f;
            float v0 = a[0] + b0, v1 = a[1] + b1, v2 = a[2] + b0, v3 = a[3] + b1;
            if (epi == 1) {
                v0 = 0.5f*v0*(1.f + erff(v0*0.70710678118654752f));
                v1 = 0.5f*v1*(1.f + erff(v1*0.70710678118654752f));
                v2 = 0.5f*v2*(1.f + erff(v2*0.70710678118654752f));
                v3 = 0.5f*v3*(1.f + erff(v3*0.70710678118654752f));
            }
            if (epi == 2) {
                v0 += add[m*N + n];     v1 += add[m*N + n + 1];
                v2 += add[(m+8)*N + n]; v3 += add[(m+8)*N + n + 1];
            }
            if (epi == 3) {
                __half* Ch = (__half*)C;
                *(uint32_t*)(Ch + m*(size_t)N + n)     = packh2(v0, v1);
                *(uint32_t*)(Ch + (m+8)*(size_t)N + n) = packh2(v2, v3);
            } else if (epi == 5) {
                long m2 = m + 8;
                float h0 = add[m*N + n],  h1v = add[m*N + n + 1];
                float h2 = add[m2*N + n], h3v = add[m2*N + n + 1];
                float x0v = g_x[m*N + n],  x1v = g_x[m*N + n + 1];
                float x2v = g_x[m2*N + n], x3v = g_x[m2*N + n + 1];
                float gt0 = g_gate[m], gt1 = g_gate[m2];
                long b0i = m >> 9,  t0 = g_idx[m];
                long b1i = m2 >> 9, t1 = g_idx[m2];
                float o0 = x0v + gt0*((v0 + h0)  - x0v);
                float o1 = x1v + gt0*((v1 + h1v) - x1v);
                float o2 = x2v + gt1*((v2 + h2)  - x2v);
                float o3 = x3v + gt1*((v3 + h3v) - x3v);
                *(float2*)(C + (b0i*TT + t0)*(long)HID + n) = make_float2(o0, o1);
                *(float2*)(C + (b1i*TT + t1)*(long)HID + n) = make_float2(o2, o3);
            } else {
                *(float2*)(C + m*N + n)     = make_float2(v0, v1);
                *(float2*)(C + (m+8)*N + n) = make_float2(v2, v3);
            }
        }
    }
}

// ================= launch =================
extern "C" void kernel_launch(void* const* d_in, const int* in_sizes, int n_in,
                              void* d_out, int out_size) {
    const float* hs     = (const float*)d_in[0];
    const float* rw     = (const float*)d_in[1];
    const float* cfc1_w = (const float*)d_in[2];
    const float* cfc1_b = (const float*)d_in[3];
    const float* cfc2_w = (const float*)d_in[4];
    const float* cfc2_b = (const float*)d_in[5];
    const float* ln1    = (const float*)d_in[6];
    const float* ln2    = (const float*)d_in[7];
    const float* q_w    = (const float*)d_in[8];
    const float* q_b    = (const float*)d_in[9];
    const float* k_w    = (const float*)d_in[10];
    const float* k_b    = (const float*)d_in[11];
    const float* v_w    = (const float*)d_in[12];
    const float* v_b    = (const float*)d_in[13];
    const float* o_w    = (const float*)d_in[14];
    const float* gate_w = (const float*)d_in[15];
    const float* up_w   = (const float*)d_in[16];
    const float* down_w = (const float*)d_in[17];
    float* out = (float*)d_out;

    float *px, *ph1, *pgu, *pact, *pqkvb;
    cudaGetSymbolAddress((void**)&px,  g_x);
    cudaGetSymbolAddress((void**)&ph1, g_h1);
    cudaGetSymbolAddress((void**)&pgu, g_gu);
    cudaGetSymbolAddress((void**)&pact, g_act);
    cudaGetSymbolAddress((void**)&pqkvb, g_qkvb);
    __half *pA, *pAp, *pB, *pqkvh;
    cudaGetSymbolAddress((void**)&pA,  g_A);
    cudaGetSymbolAddress((void**)&pAp, g_Ap);
    cudaGetSymbolAddress((void**)&pB,  g_B);
    cudaGetSymbolAddress((void**)&pqkvh, g_qkvh);

    cudaFuncSetAttribute(tc_gemm, cudaFuncAttributeMaxDynamicSharedMemorySize, GEMM_SMEM);
    cudaFuncSetAttribute(k_attn, cudaFuncAttributeMaxDynamicSharedMemorySize, ATT_SMEM);

    static bool s_init = false;
    static cudaStream_t s1, s2, s3;
    static cudaEvent_t e0, eTopk, eCfc1, eQkv, eO, eGU, eDown, eCopy, ePred;
    if (!s_init) {
        cudaStreamCreate(&s1); cudaStreamCreate(&s2); cudaStreamCreate(&s3);
        cudaEventCreateWithFlags(&e0,    cudaEventDisableTiming);
        cudaEventCreateWithFlags(&eTopk, cudaEventDisableTiming);
        cudaEventCreateWithFlags(&eCfc1, cudaEventDisableTiming);
        cudaEventCreateWithFlags(&eQkv,  cudaEventDisableTiming);
        cudaEventCreateWithFlags(&eO,    cudaEventDisableTiming);
        cudaEventCreateWithFlags(&eGU,   cudaEventDisableTiming);
        cudaEventCreateWithFlags(&eDown, cudaEventDisableTiming);
        cudaEventCreateWithFlags(&eCopy, cudaEventDisableTiming);
        cudaEventCreateWithFlags(&ePred, cudaEventDisableTiming);
        s_init = true;
    }

#define CONVB_S(st, src, dst, R, K) k_convB<<<((size_t)(R)*(K)/8)/256, 256, 0, st>>>(src, dst)
#define GEMM_S(st, Ap_, Bp_, M, N, K, bias, add, Cp, epi) \
    tc_gemm<<<dim3((N)/256, (M)/128), 256, GEMM_SMEM, st>>>(Ap_, Bp_, bias, add, Cp, M, N, K, epi)

    // ---- fork ----
    k_init<<<64, 256>>>();
    cudaEventRecord(e0, 0);
    cudaStreamWaitEvent(s1, e0, 0);
    cudaStreamWaitEvent(s2, e0, 0);
    cudaStreamWaitEvent(s3, e0, 0);

    // s1: weight conversions
    CONVB_S(s1, cfc1_w, pB + OFF_CFC1, CH, HID);
    cudaEventRecord(eCfc1, s1);
    CONVB_S(s1, q_w, pB + OFF_QKV,                     HID, HID);
    CONVB_S(s1, k_w, pB + OFF_QKV + (size_t)HID*HID,   HID, HID);
    CONVB_S(s1, v_w, pB + OFF_QKV + (size_t)2*HID*HID, HID, HID);
    k_catbias<<<QSTR/256, 256, 0, s1>>>(q_b, k_b, v_b);
    cudaEventRecord(eQkv, s1);
    CONVB_S(s1, o_w, pB + OFF_O, HID, HID);
    cudaEventRecord(eO, s1);
    CONVB_S(s1, gate_w, pB + OFF_GATE, INTER, HID);
    CONVB_S(s1, up_w,   pB + OFF_UP,   INTER, HID);
    cudaEventRecord(eGU, s1);
    CONVB_S(s1, down_w, pB + OFF_DOWN, HID, INTER);
    cudaEventRecord(eDown, s1);

    // s2: predictor chain
    CONVB_S(s2, hs, pAp, NTOT, HID);
    cudaStreamWaitEvent(s2, eCfc1, 0);
    GEMM_S(s2, pAp, pB + OFF_CFC1, NTOT, CH, HID, cfc1_b, nullptr, pact, 1);

    // s3: bulk output copy
    k_copy<<<((size_t)NTOT*HID/4)/256, 256, 0, s3>>>(hs, out);
    cudaEventRecord(eCopy, s3);

    // main: router -> radix topk -> attention block -> MLP
    k_router<<<NTOT, 256>>>(hs, rw);
    k_topk<<<BB, 1024>>>();
    cudaEventRecord(eTopk, 0);

    cudaStreamWaitEvent(s2, eTopk, 0);
    k_pred2<<<NTOT/8, 256, 0, s2>>>(cfc2_w, cfc2_b);
    cudaEventRecord(ePred, s2);

    // fused gather + rmsnorm1
    k_grms<<<NTOK, 256>>>(hs, ln1, pA);

    cudaStreamWaitEvent(0, eQkv, 0);
    GEMM_S(0, pA, pB + OFF_QKV, NTOK, QSTR, HID, pqkvb, nullptr, (float*)pqkvh, 3);
    k_rope<<<(NTOK*NHEADS*32)/256, 256>>>();
    k_attn<<<dim3(KSEL/64, BB*NHEADS), 128, ATT_SMEM>>>(pA);

    cudaStreamWaitEvent(0, eO, 0);
    GEMM_S(0, pA, pB + OFF_O, NTOK, HID, HID, nullptr, px, ph1, 2);
    k_rms<<<NTOK, 256>>>(ph1, ln2, pA);

    cudaStreamWaitEvent(0, eGU, 0);
    GEMM_S(0, pA, pB + OFF_GATE, NTOK, 2*INTER, HID, nullptr, nullptr, pgu, 0);
    k_silumul<<<(NTOK*(INTER/8))/256, 256>>>(pA);

    // down-proj with fused residual + MoD scatter directly into out
    cudaStreamWaitEvent(0, eDown, 0);
    cudaStreamWaitEvent(0, eCopy, 0);
    GEMM_S(0, pA, pB + OFF_DOWN, NTOK, HID, INTER, nullptr, ph1, out, 5);

    cudaStreamWaitEvent(0, ePred, 0);
    k_final<<<1, 32>>>(out, (long long)NTOT*HID, (long long)out_size);
}